// round 2
// baseline (speedup 1.0000x reference)
#include <cuda_runtime.h>
#include <cuda_bf16.h>
#include <cstdint>

// Problem constants
#define BWIN   512            // total windows (batch*nW)
#define NTOK   343            // tokens per window
#define DIM    96
#define NHEAD  3
#define HD     32
#define NW     64             // mask windows
#define MROWS  (BWIN * NTOK)  // 175616
#define SCALE  0.17677669529663687f  // 1/sqrt(32)

// ---------------- device scratch (allocation-free rule: __device__ globals) ----------
__device__ float g_q[BWIN * NHEAD * NTOK * HD];      // 67.4 MB, layout [(b*3+h)*343 + n]*32 + d
__device__ float g_k[BWIN * NHEAD * NTOK * HD];
__device__ float g_v[BWIN * NHEAD * NTOK * HD];
__device__ float g_att[BWIN * NTOK * DIM];           // attention output, [b,n, h*32+d]
__device__ float g_bm[NW * NHEAD * NTOK * NTOK];     // fused (mask + rel-pos bias), 90.4 MB

// ---------------- kernel 0: fuse mask + relative position bias ----------------------
__global__ void bm_kernel(const float* __restrict__ mask,
                          const float* __restrict__ rpb,
                          const int*   __restrict__ rel) {
    int idx = blockIdx.x * blockDim.x + threadIdx.x;
    const int total = NW * NHEAD * NTOK * NTOK;
    if (idx >= total) return;
    int m = idx % NTOK;
    int t = idx / NTOK;
    int n = t % NTOK;
    t /= NTOK;
    int h = t % NHEAD;
    int w = t / NHEAD;
    g_bm[idx] = mask[(w * NTOK + n) * NTOK + m] + rpb[rel[n * NTOK + m] * NHEAD + h];
}

// ---------------- generic GEMM: C[m,n] = sum_k A[m,k]*W[n,k] + bias[n] ----------------
// TM=64 rows, TN=96 cols per CTA, 384 threads (16x24), 4x4 micro-tile.
// EPI==1: qkv epilogue (route to g_q/g_k/g_v, scale q). EPI==0: plain write to out.
template <int EPI>
__global__ __launch_bounds__(384)
void gemm_kernel(const float* __restrict__ A,
                 const float* __restrict__ W,
                 const float* __restrict__ bias,
                 float* __restrict__ out) {
    extern __shared__ float sm[];
    float* At = sm;            // [96][64]  (k-major, row index inner)
    float* Wt = sm + 96 * 64;  // [96][96]

    const float* Ap = (EPI == 1) ? A : g_att;

    const int tid = threadIdx.x;
    const int m0 = blockIdx.x * 64;
    const int n0 = blockIdx.y * 96;

    // load A tile (64 rows x 96 k) transposed into At[k][row]
    for (int it = tid; it < 64 * 24; it += 384) {
        int row = it / 24, kc = (it % 24) * 4;
        float4 a = *(const float4*)&Ap[(size_t)(m0 + row) * 96 + kc];
        At[(kc + 0) * 64 + row] = a.x;
        At[(kc + 1) * 64 + row] = a.y;
        At[(kc + 2) * 64 + row] = a.z;
        At[(kc + 3) * 64 + row] = a.w;
    }
    // load W tile (96 rows x 96 k) transposed into Wt[k][n]
    for (int it = tid; it < 96 * 24; it += 384) {
        int row = it / 24, kc = (it % 24) * 4;
        float4 w = *(const float4*)&W[(size_t)(n0 + row) * 96 + kc];
        Wt[(kc + 0) * 96 + row] = w.x;
        Wt[(kc + 1) * 96 + row] = w.y;
        Wt[(kc + 2) * 96 + row] = w.z;
        Wt[(kc + 3) * 96 + row] = w.w;
    }
    __syncthreads();

    const int tx = tid % 24;  // 24 * 4 = 96 cols
    const int ty = tid / 24;  // 16 * 4 = 64 rows

    float acc[4][4] = {};
#pragma unroll 8
    for (int k = 0; k < 96; k++) {
        float4 a = *(const float4*)&At[k * 64 + ty * 4];
        float4 w = *(const float4*)&Wt[k * 96 + tx * 4];
        acc[0][0] += a.x * w.x; acc[0][1] += a.x * w.y; acc[0][2] += a.x * w.z; acc[0][3] += a.x * w.w;
        acc[1][0] += a.y * w.x; acc[1][1] += a.y * w.y; acc[1][2] += a.y * w.z; acc[1][3] += a.y * w.w;
        acc[2][0] += a.z * w.x; acc[2][1] += a.z * w.y; acc[2][2] += a.z * w.z; acc[2][3] += a.z * w.w;
        acc[3][0] += a.w * w.x; acc[3][1] += a.w * w.y; acc[3][2] += a.w * w.z; acc[3][3] += a.w * w.w;
    }

    const int ncol0 = n0 + tx * 4;                // 4-aligned, never crosses a 32-col block
    float4 b4 = *(const float4*)&bias[ncol0];

    if (EPI == 0) {
#pragma unroll
        for (int r = 0; r < 4; r++) {
            int m = m0 + ty * 4 + r;
            float4 v;
            v.x = acc[r][0] + b4.x;
            v.y = acc[r][1] + b4.y;
            v.z = acc[r][2] + b4.z;
            v.w = acc[r][3] + b4.w;
            *(float4*)&out[(size_t)m * DIM + ncol0] = v;
        }
    } else {
        const int kind = ncol0 / DIM;                 // 0=q, 1=k, 2=v
        const int hh   = (ncol0 % DIM) / HD;
        const int dd   = ncol0 % HD;                  // 4-aligned
        float* dst = (kind == 0) ? g_q : (kind == 1) ? g_k : g_v;
        const float sc = (kind == 0) ? SCALE : 1.0f;
#pragma unroll
        for (int r = 0; r < 4; r++) {
            int m = m0 + ty * 4 + r;
            int bwin = m / NTOK;
            int tok = m - bwin * NTOK;
            size_t base = ((size_t)(bwin * NHEAD + hh) * NTOK + tok) * HD + dd;
            float4 v;
            v.x = (acc[r][0] + b4.x) * sc;
            v.y = (acc[r][1] + b4.y) * sc;
            v.z = (acc[r][2] + b4.z) * sc;
            v.w = (acc[r][3] + b4.w) * sc;
            *(float4*)&dst[base] = v;
        }
    }
}

// ---------------- fused attention kernel ---------------------------------------------
// grid: (6 row-tiles, 3 heads, 512 windows), 256 threads.
// smem: Kt[32][344] + V[344][32] + Qt[32][64] + P[64][344] + inv[64]  = 184,576 B
#define TM 64
#define SKT_OFF 0                        // 32*344 = 11008 floats
#define SV_OFF  11008                    // 344*32 = 11008
#define SQT_OFF 22016                    // 32*64  = 2048
#define SP_OFF  24064                    // 64*344 = 22016
#define SINV_OFF 46080                   // 64
#define ATTN_SMEM_FLOATS 46144

__global__ __launch_bounds__(256)
void attn_kernel() {
    extern __shared__ float s[];
    float* sKt  = s + SKT_OFF;
    float* sV   = s + SV_OFF;
    float* sQt  = s + SQT_OFF;
    float* sP   = s + SP_OFF;
    float* sInv = s + SINV_OFF;

    const int tid = threadIdx.x;
    const int tile = blockIdx.x;
    const int h = blockIdx.y;
    const int b = blockIdx.z;
    const int r0 = tile * TM;
    const int w = b & (NW - 1);

    const size_t kvbase = ((size_t)(b * NHEAD + h)) * (NTOK * HD);

    // load K transposed, V row-major, Q transposed
    for (int idx = tid; idx < NTOK * HD; idx += 256) {
        int n = idx >> 5, d = idx & 31;
        float kv = g_k[kvbase + idx];
        sKt[d * 344 + n] = kv;
        sV[idx] = g_v[kvbase + idx];
    }
    if (tid < 32) sV[NTOK * HD + tid] = 0.0f;  // zero pad row 343
    for (int idx = tid; idx < TM * HD; idx += 256) {
        int i = idx >> 5, d = idx & 31;
        int r = r0 + i;
        sQt[d * 64 + i] = (r < NTOK) ? g_q[kvbase + r * HD + d] : 0.0f;
    }
    __syncthreads();

    const int tx = tid & 15;   // 16 * 4 = 64 cols per block
    const int ty = tid >> 4;   // 16 * 4 = 64 rows
    const size_t bmbase = ((size_t)(w * NHEAD + h)) * NTOK * NTOK;

    // ---- logits: S = Q K^T + (bias+mask) ----
    for (int jb = 0; jb < NTOK; jb += 64) {
        float acc[4][4] = {};
        const int jc = jb + tx * 4;
#pragma unroll 4
        for (int k = 0; k < 32; k++) {
            float4 a  = *(const float4*)&sQt[k * 64 + ty * 4];
            float4 kk = *(const float4*)&sKt[k * 344 + jc];
            acc[0][0] += a.x * kk.x; acc[0][1] += a.x * kk.y; acc[0][2] += a.x * kk.z; acc[0][3] += a.x * kk.w;
            acc[1][0] += a.y * kk.x; acc[1][1] += a.y * kk.y; acc[1][2] += a.y * kk.z; acc[1][3] += a.y * kk.w;
            acc[2][0] += a.z * kk.x; acc[2][1] += a.z * kk.y; acc[2][2] += a.z * kk.z; acc[2][3] += a.z * kk.w;
            acc[3][0] += a.w * kk.x; acc[3][1] += a.w * kk.y; acc[3][2] += a.w * kk.z; acc[3][3] += a.w * kk.w;
        }
#pragma unroll
        for (int r = 0; r < 4; r++) {
            int i = ty * 4 + r;
            int row = r0 + i;
            if (row < NTOK) {
                const float* bmrow = &g_bm[bmbase + (size_t)row * NTOK];
#pragma unroll
                for (int c = 0; c < 4; c++) {
                    int j = jc + c;
                    if (j < NTOK) sP[i * 344 + j] = acc[r][c] + bmrow[j];
                }
            }
        }
    }
    __syncthreads();

    // ---- per-row softmax (8 warps x 8 rows) ----
    const int warp = tid >> 5, lane = tid & 31;
    for (int rr = 0; rr < 8; rr++) {
        int i = warp * 8 + rr;
        int row = r0 + i;
        if (row < NTOK) {
            float* prow = &sP[i * 344];
            float mx = -1e30f;
            for (int j = lane; j < NTOK; j += 32) mx = fmaxf(mx, prow[j]);
#pragma unroll
            for (int off = 16; off > 0; off >>= 1)
                mx = fmaxf(mx, __shfl_xor_sync(0xffffffffu, mx, off));
            float sum = 0.0f;
            for (int j = lane; j < NTOK; j += 32) {
                float e = __expf(prow[j] - mx);
                prow[j] = e;
                sum += e;
            }
#pragma unroll
            for (int off = 16; off > 0; off >>= 1)
                sum += __shfl_xor_sync(0xffffffffu, sum, off);
            if (lane == 0) {
                prow[343] = 0.0f;           // zero padding column
                sInv[i] = 1.0f / sum;
            }
        }
    }
    __syncthreads();

    // ---- PV: out[i,d] = sum_j P[i,j] * V[j,d] ----
    // thread: rows ty*4..ty*4+3, cols d0 = tx*2, tx*2+1
    const int d0 = tx * 2;
    float ac0[4] = {}, ac1[4] = {};
    for (int j = 0; j < 344; j += 4) {
        float4 p0 = *(const float4*)&sP[(ty * 4 + 0) * 344 + j];
        float4 p1 = *(const float4*)&sP[(ty * 4 + 1) * 344 + j];
        float4 p2 = *(const float4*)&sP[(ty * 4 + 2) * 344 + j];
        float4 p3 = *(const float4*)&sP[(ty * 4 + 3) * 344 + j];
        float2 v0 = *(const float2*)&sV[(j + 0) * 32 + d0];
        float2 v1 = *(const float2*)&sV[(j + 1) * 32 + d0];
        float2 v2 = *(const float2*)&sV[(j + 2) * 32 + d0];
        float2 v3 = *(const float2*)&sV[(j + 3) * 32 + d0];
        ac0[0] += p0.x * v0.x; ac1[0] += p0.x * v0.y;
        ac0[1] += p1.x * v0.x; ac1[1] += p1.x * v0.y;
        ac0[2] += p2.x * v0.x; ac1[2] += p2.x * v0.y;
        ac0[3] += p3.x * v0.x; ac1[3] += p3.x * v0.y;
        ac0[0] += p0.y * v1.x; ac1[0] += p0.y * v1.y;
        ac0[1] += p1.y * v1.x; ac1[1] += p1.y * v1.y;
        ac0[2] += p2.y * v1.x; ac1[2] += p2.y * v1.y;
        ac0[3] += p3.y * v1.x; ac1[3] += p3.y * v1.y;
        ac0[0] += p0.z * v2.x; ac1[0] += p0.z * v2.y;
        ac0[1] += p1.z * v2.x; ac1[1] += p1.z * v2.y;
        ac0[2] += p2.z * v2.x; ac1[2] += p2.z * v2.y;
        ac0[3] += p3.z * v2.x; ac1[3] += p3.z * v2.y;
        ac0[0] += p0.w * v3.x; ac1[0] += p0.w * v3.y;
        ac0[1] += p1.w * v3.x; ac1[1] += p1.w * v3.y;
        ac0[2] += p2.w * v3.x; ac1[2] += p2.w * v3.y;
        ac0[3] += p3.w * v3.x; ac1[3] += p3.w * v3.y;
    }
#pragma unroll
    for (int r = 0; r < 4; r++) {
        int i = ty * 4 + r;
        int row = r0 + i;
        if (row < NTOK) {
            float inv = sInv[i];
            float2 o;
            o.x = ac0[r] * inv;
            o.y = ac1[r] * inv;
            *(float2*)&g_att[((size_t)b * NTOK + row) * DIM + h * HD + d0] = o;
        }
    }
}

// ---------------- launch --------------------------------------------------------------
extern "C" void kernel_launch(void* const* d_in, const int* in_sizes, int n_in,
                              void* d_out, int out_size) {
    const float* x      = (const float*)d_in[0];
    const float* mask   = (const float*)d_in[1];
    const float* qkv_w  = (const float*)d_in[2];
    const float* qkv_b  = (const float*)d_in[3];
    const float* proj_w = (const float*)d_in[4];
    const float* proj_b = (const float*)d_in[5];
    const float* rpb    = (const float*)d_in[6];
    const int*   rel    = (const int*)d_in[7];
    float* out = (float*)d_out;

    cudaFuncSetAttribute(gemm_kernel<0>, cudaFuncAttributeMaxDynamicSharedMemorySize, 96 * 64 * 4 + 96 * 96 * 4);
    cudaFuncSetAttribute(gemm_kernel<1>, cudaFuncAttributeMaxDynamicSharedMemorySize, 96 * 64 * 4 + 96 * 96 * 4);
    cudaFuncSetAttribute(attn_kernel, cudaFuncAttributeMaxDynamicSharedMemorySize, ATTN_SMEM_FLOATS * 4);

    // 0: fuse mask + rpb bias
    {
        const int total = NW * NHEAD * NTOK * NTOK;
        bm_kernel<<<(total + 255) / 256, 256>>>(mask, rpb, rel);
    }
    // 1: qkv GEMM -> g_q/g_k/g_v
    gemm_kernel<1><<<dim3(MROWS / 64, 3), 384, (96 * 64 + 96 * 96) * 4>>>(x, qkv_w, qkv_b, nullptr);
    // 2: fused attention -> g_att
    attn_kernel<<<dim3(6, NHEAD, BWIN), 256, ATTN_SMEM_FLOATS * 4>>>();
    // 3: proj GEMM -> d_out
    gemm_kernel<0><<<dim3(MROWS / 64, 1), 384, (96 * 64 + 96 * 96) * 4>>>(nullptr, proj_w, proj_b, out);
}

// round 5
// speedup vs baseline: 1.6619x; 1.6619x over previous
#include <cuda_runtime.h>
#include <cuda_bf16.h>
#include <cstdint>

// Problem constants
#define BWIN   512
#define NTOK   343
#define DIM    96
#define NHEAD  3
#define HD     32
#define NW     64
#define MROWS  (BWIN * NTOK)  // 175616
#define SCALE  0.17677669529663687f

// ---------------- device scratch ----------------
__device__ float g_q[BWIN * NHEAD * NTOK * HD];
__device__ float g_k[BWIN * NHEAD * NTOK * HD];
__device__ float g_v[BWIN * NHEAD * NTOK * HD];
__device__ float g_att[BWIN * NTOK * DIM];
__device__ float g_bm[NW * NHEAD * NTOK * NTOK];   // fused mask + rel-pos bias

// ---------------- helpers ----------------
__device__ __forceinline__ float to_tf32(float x) {
    uint32_t u; asm("cvt.rna.tf32.f32 %0, %1;" : "=r"(u) : "f"(x));
    return __uint_as_float(u);
}
__device__ __forceinline__ uint32_t f2tf(float x) {
    uint32_t u; asm("cvt.rna.tf32.f32 %0, %1;" : "=r"(u) : "f"(x));
    return u;
}
// D = A(16x8, row) * B(8x8, col) + D, tf32 in, fp32 accum
__device__ __forceinline__ void mma8(float* c, uint32_t a0, uint32_t a1, uint32_t a2, uint32_t a3,
                                     uint32_t b0, uint32_t b1) {
    asm volatile("mma.sync.aligned.m16n8k8.row.col.f32.tf32.tf32.f32 "
                 "{%0,%1,%2,%3}, {%4,%5,%6,%7}, {%8,%9}, {%0,%1,%2,%3};\n"
                 : "+f"(c[0]), "+f"(c[1]), "+f"(c[2]), "+f"(c[3])
                 : "r"(a0), "r"(a1), "r"(a2), "r"(a3), "r"(b0), "r"(b1));
}

// ---------------- kernel 0: fuse mask + rpb ----------------
__global__ void bm_kernel(const float* __restrict__ mask,
                          const float* __restrict__ rpb,
                          const int*   __restrict__ rel) {
    int idx = blockIdx.x * blockDim.x + threadIdx.x;
    const int total = NW * NHEAD * NTOK * NTOK;
    if (idx >= total) return;
    int m = idx % NTOK;
    int t = idx / NTOK;
    int n = t % NTOK;
    t /= NTOK;
    int h = t % NHEAD;
    int w = t / NHEAD;
    g_bm[idx] = mask[(w * NTOK + n) * NTOK + m] + rpb[rel[n * NTOK + m] * NHEAD + h];
}

// ---------------- tensor-core GEMM: C[m,n] = A[m,:] . W[n,:] + bias[n] ----------------
// CTA: 128 rows x 96 cols, 256 threads = 8 warps (4 m-groups x 2 n-groups), K=96.
// EPI==1: qkv epilogue (chunk=blockIdx.y selects q/k/v); EPI==0: proj -> out.
template <int EPI>
__global__ __launch_bounds__(256)
void gemm_tc(const float* __restrict__ A,
             const float* __restrict__ W,
             const float* __restrict__ bias,
             float* __restrict__ out) {
    extern __shared__ float sm[];
    float* sA = sm;          // [128][100]
    float* sW = sm + 12800;  // [96][100]

    const float* Ap = (EPI == 1) ? A : g_att;
    const int tid = threadIdx.x;
    const int m0 = blockIdx.x * 128;
    const int chunk = blockIdx.y;

    for (int it = tid; it < 128 * 24; it += 256) {
        int row = it / 24, k4 = (it % 24) * 4;
        float4 a = *(const float4*)&Ap[(size_t)(m0 + row) * 96 + k4];
        sA[row * 100 + k4 + 0] = to_tf32(a.x);
        sA[row * 100 + k4 + 1] = to_tf32(a.y);
        sA[row * 100 + k4 + 2] = to_tf32(a.z);
        sA[row * 100 + k4 + 3] = to_tf32(a.w);
    }
    for (int it = tid; it < 96 * 24; it += 256) {
        int row = it / 24, k4 = (it % 24) * 4;
        float4 wv = *(const float4*)&W[(size_t)(chunk * 96 + row) * 96 + k4];
        sW[row * 100 + k4 + 0] = to_tf32(wv.x);
        sW[row * 100 + k4 + 1] = to_tf32(wv.y);
        sW[row * 100 + k4 + 2] = to_tf32(wv.z);
        sW[row * 100 + k4 + 3] = to_tf32(wv.w);
    }
    __syncthreads();

    const int warp = tid >> 5, lane = tid & 31;
    const int g = lane >> 2, c4 = lane & 3;
    const int wm = warp & 3;   // 4 m-groups of 32 rows
    const int wn = warp >> 2;  // 2 n-groups of 48 cols

    float acc[2][6][4];
#pragma unroll
    for (int nt = 0; nt < 6; nt++) {
        int cc = wn * 48 + nt * 8 + 2 * c4;
        float b0 = bias[chunk * 96 + cc];
        float b1 = bias[chunk * 96 + cc + 1];
        acc[0][nt][0] = b0; acc[0][nt][1] = b1; acc[0][nt][2] = b0; acc[0][nt][3] = b1;
        acc[1][nt][0] = b0; acc[1][nt][1] = b1; acc[1][nt][2] = b0; acc[1][nt][3] = b1;
    }

#pragma unroll
    for (int ks = 0; ks < 12; ks++) {
        int kk = ks * 8;
        uint32_t a[2][4];
#pragma unroll
        for (int mt = 0; mt < 2; mt++) {
            int r = wm * 32 + mt * 16 + g;
            a[mt][0] = __float_as_uint(sA[r * 100 + kk + c4]);
            a[mt][1] = __float_as_uint(sA[(r + 8) * 100 + kk + c4]);
            a[mt][2] = __float_as_uint(sA[r * 100 + kk + c4 + 4]);
            a[mt][3] = __float_as_uint(sA[(r + 8) * 100 + kk + c4 + 4]);
        }
#pragma unroll
        for (int nt = 0; nt < 6; nt++) {
            int n = wn * 48 + nt * 8 + g;
            uint32_t b0 = __float_as_uint(sW[n * 100 + kk + c4]);
            uint32_t b1 = __float_as_uint(sW[n * 100 + kk + c4 + 4]);
            mma8(acc[0][nt], a[0][0], a[0][1], a[0][2], a[0][3], b0, b1);
            mma8(acc[1][nt], a[1][0], a[1][1], a[1][2], a[1][3], b0, b1);
        }
    }

#pragma unroll
    for (int mt = 0; mt < 2; mt++) {
        int ra = m0 + wm * 32 + mt * 16 + g;
        int rb = ra + 8;
        if (EPI == 0) {
#pragma unroll
            for (int nt = 0; nt < 6; nt++) {
                int cc = wn * 48 + nt * 8 + 2 * c4;
                *(float2*)&out[(size_t)ra * 96 + cc] = make_float2(acc[mt][nt][0], acc[mt][nt][1]);
                *(float2*)&out[(size_t)rb * 96 + cc] = make_float2(acc[mt][nt][2], acc[mt][nt][3]);
            }
        } else {
            int ba = ra / NTOK, ta = ra - ba * NTOK;
            int bb = rb / NTOK, tb = rb - bb * NTOK;
            float* dst = (chunk == 0) ? g_q : (chunk == 1) ? g_k : g_v;
            const float sc = (chunk == 0) ? SCALE : 1.0f;
#pragma unroll
            for (int nt = 0; nt < 6; nt++) {
                int cc = wn * 48 + nt * 8 + 2 * c4;
                int hh = cc >> 5, dd = cc & 31;
                *(float2*)&dst[((size_t)(ba * NHEAD + hh) * NTOK + ta) * HD + dd] =
                    make_float2(acc[mt][nt][0] * sc, acc[mt][nt][1] * sc);
                *(float2*)&dst[((size_t)(bb * NHEAD + hh) * NTOK + tb) * HD + dd] =
                    make_float2(acc[mt][nt][2] * sc, acc[mt][nt][3] * sc);
            }
        }
    }
}

// ---------------- fused attention (tensor cores) ----------------
// grid (6 row-tiles, 3 heads, 512 windows), 256 threads = 8 warps.
// smem floats: sQ 64x36, sK 344x36, sV 344x40, sS 64x348, sInv 64  => 203,136 B
#define SQ_OFF   0
#define SK_OFF   2304
#define SV_OFF   14688
#define SS_OFF   28448
#define SINV_OFF 50720
#define ATTN_SMEM_BYTES (50784 * 4)

__global__ __launch_bounds__(256)
void attn_kernel() {
    extern __shared__ float s[];
    float* sQ = s + SQ_OFF;
    float* sK = s + SK_OFF;
    float* sV = s + SV_OFF;
    float* sS = s + SS_OFF;
    float* sInv = s + SINV_OFF;

    const int tid = threadIdx.x;
    const int r0 = blockIdx.x * 64;
    const int h = blockIdx.y;
    const int b = blockIdx.z;
    const int w = b & (NW - 1);
    const size_t kvbase = ((size_t)(b * NHEAD + h)) * (NTOK * HD);
    const size_t bmbase = ((size_t)(w * NHEAD + h)) * NTOK * NTOK;

    // fill K (pad row 343=0), V, Q (pad rows 0), tf32-rounded
    for (int idx = tid; idx < 344 * 32; idx += 256) {
        int n = idx >> 5, d = idx & 31;
        float kv = (n < NTOK) ? g_k[kvbase + idx] : 0.f;
        float vv = (n < NTOK) ? g_v[kvbase + idx] : 0.f;
        sK[n * 36 + d] = to_tf32(kv);
        sV[n * 40 + d] = to_tf32(vv);
    }
    for (int idx = tid; idx < 64 * 32; idx += 256) {
        int i = idx >> 5, d = idx & 31;
        int r = r0 + i;
        sQ[i * 36 + d] = to_tf32((r < NTOK) ? g_q[kvbase + (size_t)r * 32 + d] : 0.f);
    }
    __syncthreads();

    const int warp = tid >> 5, lane = tid & 31;
    const int g = lane >> 2, c4 = lane & 3;

    // ---- S = Q K^T + (bias+mask), accumulated in tensor cores ----
    {
        const int mg = warp & 1;                 // 2 groups of 32 rows
        const int cg = warp >> 1;                // 4 col groups of 88 (last: 80)
        const int ntiles = (cg < 3) ? 11 : 10;
        const int colbase = cg * 88;

        uint32_t aQ[2][4][4];
#pragma unroll
        for (int mt = 0; mt < 2; mt++)
#pragma unroll
            for (int ks = 0; ks < 4; ks++) {
                int r = mg * 32 + mt * 16 + g;
                int k = ks * 8 + c4;
                aQ[mt][ks][0] = __float_as_uint(sQ[r * 36 + k]);
                aQ[mt][ks][1] = __float_as_uint(sQ[(r + 8) * 36 + k]);
                aQ[mt][ks][2] = __float_as_uint(sQ[r * 36 + k + 4]);
                aQ[mt][ks][3] = __float_as_uint(sQ[(r + 8) * 36 + k + 4]);
            }

        for (int nt = 0; nt < ntiles; nt++) {
            int n0 = colbase + nt * 8;
            float acc[2][4];
#pragma unroll
            for (int mt = 0; mt < 2; mt++) {
                int ra = r0 + mg * 32 + mt * 16 + g;
                int rb = ra + 8;
                int col0 = n0 + 2 * c4;
                acc[mt][0] = (ra < NTOK && col0 < NTOK)     ? g_bm[bmbase + (size_t)ra * NTOK + col0]     : 0.f;
                acc[mt][1] = (ra < NTOK && col0 + 1 < NTOK) ? g_bm[bmbase + (size_t)ra * NTOK + col0 + 1] : 0.f;
                acc[mt][2] = (rb < NTOK && col0 < NTOK)     ? g_bm[bmbase + (size_t)rb * NTOK + col0]     : 0.f;
                acc[mt][3] = (rb < NTOK && col0 + 1 < NTOK) ? g_bm[bmbase + (size_t)rb * NTOK + col0 + 1] : 0.f;
            }
#pragma unroll
            for (int ks = 0; ks < 4; ks++) {
                int kk = ks * 8;
                uint32_t b0 = __float_as_uint(sK[(n0 + g) * 36 + kk + c4]);
                uint32_t b1 = __float_as_uint(sK[(n0 + g) * 36 + kk + c4 + 4]);
                mma8(acc[0], aQ[0][ks][0], aQ[0][ks][1], aQ[0][ks][2], aQ[0][ks][3], b0, b1);
                mma8(acc[1], aQ[1][ks][0], aQ[1][ks][1], aQ[1][ks][2], aQ[1][ks][3], b0, b1);
            }
#pragma unroll
            for (int mt = 0; mt < 2; mt++) {
                int lr = mg * 32 + mt * 16 + g;
                *(float2*)&sS[lr * 348 + n0 + 2 * c4] = make_float2(acc[mt][0], acc[mt][1]);
                *(float2*)&sS[(lr + 8) * 348 + n0 + 2 * c4] = make_float2(acc[mt][2], acc[mt][3]);
            }
        }
    }
    __syncthreads();

    // ---- softmax: 8 warps x 8 rows ----
    for (int rr = 0; rr < 8; rr++) {
        int i = warp * 8 + rr;
        int row = r0 + i;
        if (row < NTOK) {
            float* prow = &sS[i * 348];
            float mx = -1e30f;
            for (int j = lane; j < NTOK; j += 32) mx = fmaxf(mx, prow[j]);
#pragma unroll
            for (int off = 16; off; off >>= 1) mx = fmaxf(mx, __shfl_xor_sync(0xffffffffu, mx, off));
            float sum = 0.f;
            for (int j = lane; j < NTOK; j += 32) {
                float e = __expf(prow[j] - mx);
                prow[j] = e;
                sum += e;
            }
#pragma unroll
            for (int off = 16; off; off >>= 1) sum += __shfl_xor_sync(0xffffffffu, sum, off);
            if (lane == 0) { prow[343] = 0.f; sInv[i] = 1.f / sum; }
        } else if (lane == 0) {
            sS[i * 348 + 343] = 0.f;
            sInv[i] = 0.f;
        }
    }
    __syncthreads();

    // ---- O = P V (tensor cores) ----
    {
        const int mt = warp & 3;   // 4 m-tiles of 16 rows
        const int np = warp >> 2;  // 2 n-pairs of 16 cols
        float o[2][4] = {};
        for (int ks = 0; ks < 43; ks++) {
            int j = ks * 8;
            int ra = mt * 16 + g;
            uint32_t a0 = f2tf(sS[ra * 348 + j + c4]);
            uint32_t a1 = f2tf(sS[(ra + 8) * 348 + j + c4]);
            uint32_t a2 = f2tf(sS[ra * 348 + j + c4 + 4]);
            uint32_t a3 = f2tf(sS[(ra + 8) * 348 + j + c4 + 4]);
#pragma unroll
            for (int t = 0; t < 2; t++) {
                int d0 = (np * 2 + t) * 8;
                uint32_t b0 = __float_as_uint(sV[(j + c4) * 40 + d0 + g]);
                uint32_t b1 = __float_as_uint(sV[(j + c4 + 4) * 40 + d0 + g]);
                mma8(o[t], a0, a1, a2, a3, b0, b1);
            }
        }
#pragma unroll
        for (int t = 0; t < 2; t++) {
            int d0 = (np * 2 + t) * 8 + 2 * c4;
            int lra = mt * 16 + g;
            int ra = r0 + lra;
            if (ra < NTOK) {
                float inv = sInv[lra];
                *(float2*)&g_att[((size_t)b * NTOK + ra) * DIM + h * HD + d0] =
                    make_float2(o[t][0] * inv, o[t][1] * inv);
            }
            int lrb = lra + 8, rb = r0 + lrb;
            if (rb < NTOK) {
                float inv = sInv[lrb];
                *(float2*)&g_att[((size_t)b * NTOK + rb) * DIM + h * HD + d0] =
                    make_float2(o[t][2] * inv, o[t][3] * inv);
            }
        }
    }
}

// ---------------- launch ----------------
extern "C" void kernel_launch(void* const* d_in, const int* in_sizes, int n_in,
                              void* d_out, int out_size) {
    const float* x      = (const float*)d_in[0];
    const float* mask   = (const float*)d_in[1];
    const float* qkv_w  = (const float*)d_in[2];
    const float* qkv_b  = (const float*)d_in[3];
    const float* proj_w = (const float*)d_in[4];
    const float* proj_b = (const float*)d_in[5];
    const float* rpb    = (const float*)d_in[6];
    const int*   rel    = (const int*)d_in[7];
    float* out = (float*)d_out;

    const int gemm_smem = (12800 + 9600) * 4;
    cudaFuncSetAttribute(gemm_tc<0>, cudaFuncAttributeMaxDynamicSharedMemorySize, gemm_smem);
    cudaFuncSetAttribute(gemm_tc<1>, cudaFuncAttributeMaxDynamicSharedMemorySize, gemm_smem);
    cudaFuncSetAttribute(attn_kernel, cudaFuncAttributeMaxDynamicSharedMemorySize, ATTN_SMEM_BYTES);

    {
        const int total = NW * NHEAD * NTOK * NTOK;
        bm_kernel<<<(total + 255) / 256, 256>>>(mask, rpb, rel);
    }
    gemm_tc<1><<<dim3(MROWS / 128, 3), 256, gemm_smem>>>(x, qkv_w, qkv_b, nullptr);
    attn_kernel<<<dim3(6, NHEAD, BWIN), 256, ATTN_SMEM_BYTES>>>();
    gemm_tc<0><<<dim3(MROWS / 128, 1), 256, gemm_smem>>>(nullptr, proj_w, proj_b, out);
}

// round 6
// speedup vs baseline: 2.4193x; 1.4557x over previous
#include <cuda_runtime.h>
#include <cuda_bf16.h>
#include <cstdint>

// Problem constants
#define BWIN   512
#define NTOK   343
#define DIM    96
#define NHEAD  3
#define HD     32
#define NW     64
#define MROWS  (BWIN * NTOK)  // 175616
#define SCALE  0.17677669529663687f
#define BMSTR  344            // padded bias row stride (col 343 = -1e30)

// ---------------- device scratch ----------------
__device__ float g_q[BWIN * NHEAD * NTOK * HD];
__device__ float g_k[BWIN * NHEAD * NTOK * HD];
__device__ float g_v[BWIN * NHEAD * NTOK * HD];
__device__ float g_att[BWIN * NTOK * DIM];
__device__ float g_bm[NW * NHEAD * NTOK * BMSTR];   // fused mask + rpb, padded

// ---------------- helpers ----------------
__device__ __forceinline__ float to_tf32(float x) {
    uint32_t u; asm("cvt.rna.tf32.f32 %0, %1;" : "=r"(u) : "f"(x));
    return __uint_as_float(u);
}
__device__ __forceinline__ uint32_t f2tf(float x) {
    uint32_t u; asm("cvt.rna.tf32.f32 %0, %1;" : "=r"(u) : "f"(x));
    return u;
}
__device__ __forceinline__ void mma8(float* c, uint32_t a0, uint32_t a1, uint32_t a2, uint32_t a3,
                                     uint32_t b0, uint32_t b1) {
    asm volatile("mma.sync.aligned.m16n8k8.row.col.f32.tf32.tf32.f32 "
                 "{%0,%1,%2,%3}, {%4,%5,%6,%7}, {%8,%9}, {%0,%1,%2,%3};\n"
                 : "+f"(c[0]), "+f"(c[1]), "+f"(c[2]), "+f"(c[3])
                 : "r"(a0), "r"(a1), "r"(a2), "r"(a3), "r"(b0), "r"(b1));
}

// ---------------- kernel 0: fuse mask + rpb (padded stride 344) ----------------
__global__ void bm_kernel(const float* __restrict__ mask,
                          const float* __restrict__ rpb,
                          const int*   __restrict__ rel) {
    int idx = blockIdx.x * blockDim.x + threadIdx.x;
    const int total = NW * NHEAD * NTOK * BMSTR;
    if (idx >= total) return;
    int m = idx % BMSTR;
    int t = idx / BMSTR;
    int n = t % NTOK;
    t /= NTOK;
    int h = t % NHEAD;
    int w = t / NHEAD;
    float v;
    if (m >= NTOK) v = -1e30f;
    else v = mask[(w * NTOK + n) * NTOK + m] + rpb[rel[n * NTOK + m] * NHEAD + h];
    g_bm[idx] = v;
}

// ---------------- tensor-core GEMM (same as R2) ----------------
template <int EPI>
__global__ __launch_bounds__(256)
void gemm_tc(const float* __restrict__ A,
             const float* __restrict__ W,
             const float* __restrict__ bias,
             float* __restrict__ out) {
    extern __shared__ float sm[];
    float* sA = sm;          // [128][100]
    float* sW = sm + 12800;  // [96][100]

    const float* Ap = (EPI == 1) ? A : g_att;
    const int tid = threadIdx.x;
    const int m0 = blockIdx.x * 128;
    const int chunk = blockIdx.y;

    for (int it = tid; it < 128 * 24; it += 256) {
        int row = it / 24, k4 = (it % 24) * 4;
        float4 a = *(const float4*)&Ap[(size_t)(m0 + row) * 96 + k4];
        sA[row * 100 + k4 + 0] = to_tf32(a.x);
        sA[row * 100 + k4 + 1] = to_tf32(a.y);
        sA[row * 100 + k4 + 2] = to_tf32(a.z);
        sA[row * 100 + k4 + 3] = to_tf32(a.w);
    }
    for (int it = tid; it < 96 * 24; it += 256) {
        int row = it / 24, k4 = (it % 24) * 4;
        float4 wv = *(const float4*)&W[(size_t)(chunk * 96 + row) * 96 + k4];
        sW[row * 100 + k4 + 0] = to_tf32(wv.x);
        sW[row * 100 + k4 + 1] = to_tf32(wv.y);
        sW[row * 100 + k4 + 2] = to_tf32(wv.z);
        sW[row * 100 + k4 + 3] = to_tf32(wv.w);
    }
    __syncthreads();

    const int warp = tid >> 5, lane = tid & 31;
    const int g = lane >> 2, c4 = lane & 3;
    const int wm = warp & 3;
    const int wn = warp >> 2;

    float acc[2][6][4];
#pragma unroll
    for (int nt = 0; nt < 6; nt++) {
        int cc = wn * 48 + nt * 8 + 2 * c4;
        float b0 = bias[chunk * 96 + cc];
        float b1 = bias[chunk * 96 + cc + 1];
        acc[0][nt][0] = b0; acc[0][nt][1] = b1; acc[0][nt][2] = b0; acc[0][nt][3] = b1;
        acc[1][nt][0] = b0; acc[1][nt][1] = b1; acc[1][nt][2] = b0; acc[1][nt][3] = b1;
    }

#pragma unroll
    for (int ks = 0; ks < 12; ks++) {
        int kk = ks * 8;
        uint32_t a[2][4];
#pragma unroll
        for (int mt = 0; mt < 2; mt++) {
            int r = wm * 32 + mt * 16 + g;
            a[mt][0] = __float_as_uint(sA[r * 100 + kk + c4]);
            a[mt][1] = __float_as_uint(sA[(r + 8) * 100 + kk + c4]);
            a[mt][2] = __float_as_uint(sA[r * 100 + kk + c4 + 4]);
            a[mt][3] = __float_as_uint(sA[(r + 8) * 100 + kk + c4 + 4]);
        }
#pragma unroll
        for (int nt = 0; nt < 6; nt++) {
            int n = wn * 48 + nt * 8 + g;
            uint32_t b0 = __float_as_uint(sW[n * 100 + kk + c4]);
            uint32_t b1 = __float_as_uint(sW[n * 100 + kk + c4 + 4]);
            mma8(acc[0][nt], a[0][0], a[0][1], a[0][2], a[0][3], b0, b1);
            mma8(acc[1][nt], a[1][0], a[1][1], a[1][2], a[1][3], b0, b1);
        }
    }

#pragma unroll
    for (int mt = 0; mt < 2; mt++) {
        int ra = m0 + wm * 32 + mt * 16 + g;
        int rb = ra + 8;
        if (EPI == 0) {
#pragma unroll
            for (int nt = 0; nt < 6; nt++) {
                int cc = wn * 48 + nt * 8 + 2 * c4;
                *(float2*)&out[(size_t)ra * 96 + cc] = make_float2(acc[mt][nt][0], acc[mt][nt][1]);
                *(float2*)&out[(size_t)rb * 96 + cc] = make_float2(acc[mt][nt][2], acc[mt][nt][3]);
            }
        } else {
            int ba = ra / NTOK, ta = ra - ba * NTOK;
            int bb = rb / NTOK, tb = rb - bb * NTOK;
            float* dst = (chunk == 0) ? g_q : (chunk == 1) ? g_k : g_v;
            const float sc = (chunk == 0) ? SCALE : 1.0f;
#pragma unroll
            for (int nt = 0; nt < 6; nt++) {
                int cc = wn * 48 + nt * 8 + 2 * c4;
                int hh = cc >> 5, dd = cc & 31;
                *(float2*)&dst[((size_t)(ba * NHEAD + hh) * NTOK + ta) * HD + dd] =
                    make_float2(acc[mt][nt][0] * sc, acc[mt][nt][1] * sc);
                *(float2*)&dst[((size_t)(bb * NHEAD + hh) * NTOK + tb) * HD + dd] =
                    make_float2(acc[mt][nt][2] * sc, acc[mt][nt][3] * sc);
            }
        }
    }
}

// ---------------- flash attention: warp-independent online softmax ----------------
// smem floats: sK 344x36 = 12384, sV 344x40 = 13760, sS 8 warps x 16 x 68 = 8704
#define STR_S   68
#define SV_OFF  12384
#define SS_OFF  26144
#define FL_SMEM_BYTES ((26144 + 8 * 16 * STR_S) * 4)   // 139,392 B

template <int NTC>
__device__ __forceinline__ void flash_chunk(
    int jb, const float* __restrict__ sK, const float* __restrict__ sV,
    float* __restrict__ sSw,
    const uint32_t aQ[4][4], float O[4][4],
    float& m0, float& m1, float& l0, float& l1,
    const float* __restrict__ bmA, const float* __restrict__ bmB,
    int g, int c4)
{
    // prefetch bias (overlaps with MMA below)
    float2 bA[NTC], bB[NTC];
#pragma unroll
    for (int nt = 0; nt < NTC; nt++) {
        int c0 = jb + nt * 8 + 2 * c4;
        bA[nt] = *(const float2*)&bmA[c0];
        bB[nt] = *(const float2*)&bmB[c0];
    }
    // S = Q K^T
    float acc[NTC][4];
#pragma unroll
    for (int nt = 0; nt < NTC; nt++) {
        acc[nt][0] = acc[nt][1] = acc[nt][2] = acc[nt][3] = 0.f;
        int n0 = jb + nt * 8;
#pragma unroll
        for (int ks = 0; ks < 4; ks++) {
            uint32_t b0 = __float_as_uint(sK[(n0 + g) * 36 + ks * 8 + c4]);
            uint32_t b1 = __float_as_uint(sK[(n0 + g) * 36 + ks * 8 + c4 + 4]);
            mma8(acc[nt], aQ[ks][0], aQ[ks][1], aQ[ks][2], aQ[ks][3], b0, b1);
        }
        acc[nt][0] += bA[nt].x; acc[nt][1] += bA[nt].y;
        acc[nt][2] += bB[nt].x; acc[nt][3] += bB[nt].y;
    }
    // chunk row max
    float cm0 = -1e30f, cm1 = -1e30f;
#pragma unroll
    for (int nt = 0; nt < NTC; nt++) {
        cm0 = fmaxf(cm0, fmaxf(acc[nt][0], acc[nt][1]));
        cm1 = fmaxf(cm1, fmaxf(acc[nt][2], acc[nt][3]));
    }
    cm0 = fmaxf(cm0, __shfl_xor_sync(0xffffffffu, cm0, 1));
    cm0 = fmaxf(cm0, __shfl_xor_sync(0xffffffffu, cm0, 2));
    cm1 = fmaxf(cm1, __shfl_xor_sync(0xffffffffu, cm1, 1));
    cm1 = fmaxf(cm1, __shfl_xor_sync(0xffffffffu, cm1, 2));
    float mn0 = fmaxf(m0, cm0), mn1 = fmaxf(m1, cm1);
    float f0 = __expf(m0 - mn0), f1 = __expf(m1 - mn1);
    m0 = mn0; m1 = mn1;
    // exp + stage P (tf32-rounded) to smem
    float s0 = 0.f, s1 = 0.f;
#pragma unroll
    for (int nt = 0; nt < NTC; nt++) {
        float p0 = __uint_as_float(f2tf(__expf(acc[nt][0] - m0)));
        float p1 = __uint_as_float(f2tf(__expf(acc[nt][1] - m0)));
        float p2 = __uint_as_float(f2tf(__expf(acc[nt][2] - m1)));
        float p3 = __uint_as_float(f2tf(__expf(acc[nt][3] - m1)));
        s0 += p0 + p1; s1 += p2 + p3;
        *(float2*)&sSw[g * STR_S + nt * 8 + 2 * c4] = make_float2(p0, p1);
        *(float2*)&sSw[(g + 8) * STR_S + nt * 8 + 2 * c4] = make_float2(p2, p3);
    }
    s0 += __shfl_xor_sync(0xffffffffu, s0, 1);
    s0 += __shfl_xor_sync(0xffffffffu, s0, 2);
    s1 += __shfl_xor_sync(0xffffffffu, s1, 1);
    s1 += __shfl_xor_sync(0xffffffffu, s1, 2);
    l0 = l0 * f0 + s0; l1 = l1 * f1 + s1;
#pragma unroll
    for (int nt = 0; nt < 4; nt++) {
        O[nt][0] *= f0; O[nt][1] *= f0; O[nt][2] *= f1; O[nt][3] *= f1;
    }
    __syncwarp();
    // O += P V
#pragma unroll
    for (int ks = 0; ks < NTC; ks++) {
        int j = ks * 8;
        uint32_t a0 = __float_as_uint(sSw[g * STR_S + j + c4]);
        uint32_t a1 = __float_as_uint(sSw[(g + 8) * STR_S + j + c4]);
        uint32_t a2 = __float_as_uint(sSw[g * STR_S + j + c4 + 4]);
        uint32_t a3 = __float_as_uint(sSw[(g + 8) * STR_S + j + c4 + 4]);
#pragma unroll
        for (int nt = 0; nt < 4; nt++) {
            uint32_t b0 = __float_as_uint(sV[(jb + j + c4) * 40 + nt * 8 + g]);
            uint32_t b1 = __float_as_uint(sV[(jb + j + c4 + 4) * 40 + nt * 8 + g]);
            mma8(O[nt], a0, a1, a2, a3, b0, b1);
        }
    }
    __syncwarp();
}

__global__ __launch_bounds__(256)
void attn_flash() {
    extern __shared__ float s[];
    float* sK = s;
    float* sV = s + SV_OFF;

    const int tid = threadIdx.x;
    const int warp = tid >> 5, lane = tid & 31;
    float* sSw = s + SS_OFF + warp * (16 * STR_S);
    const int g = lane >> 2, c4 = lane & 3;
    const int h = blockIdx.y, b = blockIdx.z;
    const int w = b & (NW - 1);
    const size_t kvbase = (size_t)(b * NHEAD + h) * (NTOK * HD);

    // fill K/V (tf32-rounded, padded row 343 = 0)
    for (int i4 = tid; i4 < 344 * 8; i4 += 256) {
        int n = i4 >> 3, d4 = (i4 & 7) << 2;
        float4 kk, vv;
        if (n < NTOK) {
            kk = *(const float4*)&g_k[kvbase + (size_t)n * HD + d4];
            vv = *(const float4*)&g_v[kvbase + (size_t)n * HD + d4];
        } else {
            kk = make_float4(0.f, 0.f, 0.f, 0.f);
            vv = kk;
        }
        sK[n * 36 + d4 + 0] = to_tf32(kk.x);
        sK[n * 36 + d4 + 1] = to_tf32(kk.y);
        sK[n * 36 + d4 + 2] = to_tf32(kk.z);
        sK[n * 36 + d4 + 3] = to_tf32(kk.w);
        sV[n * 40 + d4 + 0] = to_tf32(vv.x);
        sV[n * 40 + d4 + 1] = to_tf32(vv.y);
        sV[n * 40 + d4 + 2] = to_tf32(vv.z);
        sV[n * 40 + d4 + 3] = to_tf32(vv.w);
    }
    __syncthreads();

    const int qrow0 = blockIdx.x * 128 + warp * 16;
    if (qrow0 >= NTOK) return;   // dead warps: safe, no CTA syncs remain

    const int ra = qrow0 + g, rb = ra + 8;
    const int rca = (ra < NTOK) ? ra : 0;
    const int rcb = (rb < NTOK) ? rb : 0;

    // Q fragments from global
    uint32_t aQ[4][4];
    {
        const float* qp = g_q + kvbase;
#pragma unroll
        for (int ks = 0; ks < 4; ks++) {
            aQ[ks][0] = f2tf(qp[(size_t)rca * HD + ks * 8 + c4]);
            aQ[ks][1] = f2tf(qp[(size_t)rcb * HD + ks * 8 + c4]);
            aQ[ks][2] = f2tf(qp[(size_t)rca * HD + ks * 8 + c4 + 4]);
            aQ[ks][3] = f2tf(qp[(size_t)rcb * HD + ks * 8 + c4 + 4]);
        }
    }
    const float* bm0 = g_bm + (size_t)((w * NHEAD + h) * NTOK) * BMSTR;
    const float* bmA = bm0 + (size_t)rca * BMSTR;
    const float* bmB = bm0 + (size_t)rcb * BMSTR;

    float O[4][4] = {};
    float m0 = -1e30f, m1 = -1e30f, l0 = 0.f, l1 = 0.f;

#pragma unroll 1
    for (int jb = 0; jb < 320; jb += 64)
        flash_chunk<8>(jb, sK, sV, sSw, aQ, O, m0, m1, l0, l1, bmA, bmB, g, c4);
    flash_chunk<3>(320, sK, sV, sSw, aQ, O, m0, m1, l0, l1, bmA, bmB, g, c4);

    // epilogue
    const float i0 = 1.f / l0, i1 = 1.f / l1;
#pragma unroll
    for (int nt = 0; nt < 4; nt++) {
        int dc = h * HD + nt * 8 + 2 * c4;
        if (ra < NTOK)
            *(float2*)&g_att[((size_t)b * NTOK + ra) * DIM + dc] =
                make_float2(O[nt][0] * i0, O[nt][1] * i0);
        if (rb < NTOK)
            *(float2*)&g_att[((size_t)b * NTOK + rb) * DIM + dc] =
                make_float2(O[nt][2] * i1, O[nt][3] * i1);
    }
}

// ---------------- launch ----------------
extern "C" void kernel_launch(void* const* d_in, const int* in_sizes, int n_in,
                              void* d_out, int out_size) {
    const float* x      = (const float*)d_in[0];
    const float* mask   = (const float*)d_in[1];
    const float* qkv_w  = (const float*)d_in[2];
    const float* qkv_b  = (const float*)d_in[3];
    const float* proj_w = (const float*)d_in[4];
    const float* proj_b = (const float*)d_in[5];
    const float* rpb    = (const float*)d_in[6];
    const int*   rel    = (const int*)d_in[7];
    float* out = (float*)d_out;

    const int gemm_smem = (12800 + 9600) * 4;
    cudaFuncSetAttribute(gemm_tc<0>, cudaFuncAttributeMaxDynamicSharedMemorySize, gemm_smem);
    cudaFuncSetAttribute(gemm_tc<1>, cudaFuncAttributeMaxDynamicSharedMemorySize, gemm_smem);
    cudaFuncSetAttribute(attn_flash, cudaFuncAttributeMaxDynamicSharedMemorySize, FL_SMEM_BYTES);

    {
        const int total = NW * NHEAD * NTOK * BMSTR;
        bm_kernel<<<(total + 255) / 256, 256>>>(mask, rpb, rel);
    }
    gemm_tc<1><<<dim3(MROWS / 128, 3), 256, gemm_smem>>>(x, qkv_w, qkv_b, nullptr);
    attn_flash<<<dim3(3, NHEAD, BWIN), 256, FL_SMEM_BYTES>>>();
    gemm_tc<0><<<dim3(MROWS / 128, 1), 256, gemm_smem>>>(nullptr, proj_w, proj_b, out);
}

// round 7
// speedup vs baseline: 4.1865x; 1.7305x over previous
#include <cuda_runtime.h>
#include <cuda_bf16.h>
#include <cstdint>

// Problem constants
#define BWIN   512
#define NTOK   343
#define DIM    96
#define NHEAD  3
#define HD     32
#define NW     64
#define MROWS  (BWIN * NTOK)  // 175616
#define LOG2E  1.4426950408889634f
#define QSCALE (0.17677669529663687f * LOG2E)   // fold log2e into q
#define BMSTR  344

// ---------------- device scratch ----------------
__device__ float g_q[BWIN * NHEAD * NTOK * HD];
__device__ float g_k[BWIN * NHEAD * NTOK * HD];
__device__ float g_v[BWIN * NHEAD * NTOK * HD];
__device__ float g_att[BWIN * NTOK * DIM];
__device__ float g_bm[NW * NHEAD * NTOK * BMSTR];   // (mask + rpb) * log2e, padded

// ---------------- helpers ----------------
__device__ __forceinline__ float to_tf32(float x) {
    uint32_t u; asm("cvt.rna.tf32.f32 %0, %1;" : "=r"(u) : "f"(x));
    return __uint_as_float(u);
}
__device__ __forceinline__ uint32_t f2tf(float x) {
    uint32_t u; asm("cvt.rna.tf32.f32 %0, %1;" : "=r"(u) : "f"(x));
    return u;
}
__device__ __forceinline__ void mma8(float* c, uint32_t a0, uint32_t a1, uint32_t a2, uint32_t a3,
                                     uint32_t b0, uint32_t b1) {
    asm volatile("mma.sync.aligned.m16n8k8.row.col.f32.tf32.tf32.f32 "
                 "{%0,%1,%2,%3}, {%4,%5,%6,%7}, {%8,%9}, {%0,%1,%2,%3};\n"
                 : "+f"(c[0]), "+f"(c[1]), "+f"(c[2]), "+f"(c[3])
                 : "r"(a0), "r"(a1), "r"(a2), "r"(a3), "r"(b0), "r"(b1));
}

// ---------------- kernel 0: fuse mask + rpb, scale by log2e ----------------
__global__ void bm_kernel(const float* __restrict__ mask,
                          const float* __restrict__ rpb,
                          const int*   __restrict__ rel) {
    int idx = blockIdx.x * blockDim.x + threadIdx.x;
    const int total = NW * NHEAD * NTOK * BMSTR;
    if (idx >= total) return;
    int m = idx % BMSTR;
    int t = idx / BMSTR;
    int n = t % NTOK;
    t /= NTOK;
    int h = t % NHEAD;
    int w = t / NHEAD;
    float v;
    if (m >= NTOK) v = -1e30f;
    else v = (mask[(w * NTOK + n) * NTOK + m] + rpb[rel[n * NTOK + m] * NHEAD + h]) * LOG2E;
    g_bm[idx] = v;
}

// ---------------- tensor-core GEMM: 64-row tiles, 3 CTAs/SM ----------------
// CTA: 64 rows x 96 cols, 256 threads = 8 warps (4 m x 2 n), warp = 16x48.
template <int EPI>
__global__ __launch_bounds__(256)
void gemm_tc(const float* __restrict__ A,
             const float* __restrict__ W,
             const float* __restrict__ bias,
             float* __restrict__ out) {
    extern __shared__ float sm[];
    float* sA = sm;         // [64][100]
    float* sW = sm + 6400;  // [96][100]

    const float* Ap = (EPI == 1) ? A : g_att;
    const int tid = threadIdx.x;
    const int m0 = blockIdx.x * 64;
    const int chunk = blockIdx.y;

    for (int it = tid; it < 64 * 24; it += 256) {
        int row = it / 24, k4 = (it % 24) * 4;
        float4 a = *(const float4*)&Ap[(size_t)(m0 + row) * 96 + k4];
        sA[row * 100 + k4 + 0] = to_tf32(a.x);
        sA[row * 100 + k4 + 1] = to_tf32(a.y);
        sA[row * 100 + k4 + 2] = to_tf32(a.z);
        sA[row * 100 + k4 + 3] = to_tf32(a.w);
    }
    for (int it = tid; it < 96 * 24; it += 256) {
        int row = it / 24, k4 = (it % 24) * 4;
        float4 wv = *(const float4*)&W[(size_t)(chunk * 96 + row) * 96 + k4];
        sW[row * 100 + k4 + 0] = to_tf32(wv.x);
        sW[row * 100 + k4 + 1] = to_tf32(wv.y);
        sW[row * 100 + k4 + 2] = to_tf32(wv.z);
        sW[row * 100 + k4 + 3] = to_tf32(wv.w);
    }
    __syncthreads();

    const int warp = tid >> 5, lane = tid & 31;
    const int g = lane >> 2, c4 = lane & 3;
    const int wm = warp & 3;   // 4 m-groups of 16 rows
    const int wn = warp >> 2;  // 2 n-groups of 48 cols

    float acc[6][4];
#pragma unroll
    for (int nt = 0; nt < 6; nt++) {
        int cc = wn * 48 + nt * 8 + 2 * c4;
        float b0 = bias[chunk * 96 + cc];
        float b1 = bias[chunk * 96 + cc + 1];
        acc[nt][0] = b0; acc[nt][1] = b1; acc[nt][2] = b0; acc[nt][3] = b1;
    }

#pragma unroll
    for (int ks = 0; ks < 12; ks++) {
        int kk = ks * 8;
        int r = wm * 16 + g;
        uint32_t a0 = __float_as_uint(sA[r * 100 + kk + c4]);
        uint32_t a1 = __float_as_uint(sA[(r + 8) * 100 + kk + c4]);
        uint32_t a2 = __float_as_uint(sA[r * 100 + kk + c4 + 4]);
        uint32_t a3 = __float_as_uint(sA[(r + 8) * 100 + kk + c4 + 4]);
#pragma unroll
        for (int nt = 0; nt < 6; nt++) {
            int n = wn * 48 + nt * 8 + g;
            uint32_t b0 = __float_as_uint(sW[n * 100 + kk + c4]);
            uint32_t b1 = __float_as_uint(sW[n * 100 + kk + c4 + 4]);
            mma8(acc[nt], a0, a1, a2, a3, b0, b1);
        }
    }

    int ra = m0 + wm * 16 + g;
    int rb = ra + 8;
    if (EPI == 0) {
#pragma unroll
        for (int nt = 0; nt < 6; nt++) {
            int cc = wn * 48 + nt * 8 + 2 * c4;
            *(float2*)&out[(size_t)ra * 96 + cc] = make_float2(acc[nt][0], acc[nt][1]);
            *(float2*)&out[(size_t)rb * 96 + cc] = make_float2(acc[nt][2], acc[nt][3]);
        }
    } else {
        int ba = ra / NTOK, ta = ra - ba * NTOK;
        int bb = rb / NTOK, tb = rb - bb * NTOK;
        float* dst = (chunk == 0) ? g_q : (chunk == 1) ? g_k : g_v;
        const float sc = (chunk == 0) ? QSCALE : 1.0f;
#pragma unroll
        for (int nt = 0; nt < 6; nt++) {
            int cc = wn * 48 + nt * 8 + 2 * c4;
            int hh = cc >> 5, dd = cc & 31;
            *(float2*)&dst[((size_t)(ba * NHEAD + hh) * NTOK + ta) * HD + dd] =
                make_float2(acc[nt][0] * sc, acc[nt][1] * sc);
            *(float2*)&dst[((size_t)(bb * NHEAD + hh) * NTOK + tb) * HD + dd] =
                make_float2(acc[nt][2] * sc, acc[nt][3] * sc);
        }
    }
}

// ---------------- flash attention: 12 warps, 192-row q-tiles ----------------
// smem floats: sK 344x36=12384, sV 344x40=13760, sQ 192x36=6912, sS 12x16x68=13056
#define STR_S   68
#define SV_OFF  12384
#define SQ_OFF  26144
#define SS_OFF  33056
#define FL_SMEM_BYTES ((SS_OFF + 12 * 16 * STR_S) * 4)   // 184,448 B

template <int NTC>
__device__ __forceinline__ void flash_chunk(
    int jb, const float* __restrict__ sK, const float* __restrict__ sV,
    float* __restrict__ sSw,
    const uint32_t aQ[4][4], float O[4][4],
    float& m0, float& m1, float& l0, float& l1,
    const float* __restrict__ bmA, const float* __restrict__ bmB,
    int g, int c4)
{
    float2 bA[NTC], bB[NTC];
#pragma unroll
    for (int nt = 0; nt < NTC; nt++) {
        int c0 = jb + nt * 8 + 2 * c4;
        bA[nt] = *(const float2*)&bmA[c0];
        bB[nt] = *(const float2*)&bmB[c0];
    }
    float acc[NTC][4];
#pragma unroll
    for (int nt = 0; nt < NTC; nt++) {
        acc[nt][0] = acc[nt][1] = acc[nt][2] = acc[nt][3] = 0.f;
        int n0 = jb + nt * 8;
#pragma unroll
        for (int ks = 0; ks < 4; ks++) {
            uint32_t b0 = __float_as_uint(sK[(n0 + g) * 36 + ks * 8 + c4]);
            uint32_t b1 = __float_as_uint(sK[(n0 + g) * 36 + ks * 8 + c4 + 4]);
            mma8(acc[nt], aQ[ks][0], aQ[ks][1], aQ[ks][2], aQ[ks][3], b0, b1);
        }
        acc[nt][0] += bA[nt].x; acc[nt][1] += bA[nt].y;
        acc[nt][2] += bB[nt].x; acc[nt][3] += bB[nt].y;
    }
    float cm0 = -1e30f, cm1 = -1e30f;
#pragma unroll
    for (int nt = 0; nt < NTC; nt++) {
        cm0 = fmaxf(cm0, fmaxf(acc[nt][0], acc[nt][1]));
        cm1 = fmaxf(cm1, fmaxf(acc[nt][2], acc[nt][3]));
    }
    cm0 = fmaxf(cm0, __shfl_xor_sync(0xffffffffu, cm0, 1));
    cm0 = fmaxf(cm0, __shfl_xor_sync(0xffffffffu, cm0, 2));
    cm1 = fmaxf(cm1, __shfl_xor_sync(0xffffffffu, cm1, 1));
    cm1 = fmaxf(cm1, __shfl_xor_sync(0xffffffffu, cm1, 2));
    float mn0 = fmaxf(m0, cm0), mn1 = fmaxf(m1, cm1);
    float f0 = exp2f(m0 - mn0), f1 = exp2f(m1 - mn1);
    m0 = mn0; m1 = mn1;
    float s0 = 0.f, s1 = 0.f;
#pragma unroll
    for (int nt = 0; nt < NTC; nt++) {
        float p0 = __uint_as_float(f2tf(exp2f(acc[nt][0] - m0)));
        float p1 = __uint_as_float(f2tf(exp2f(acc[nt][1] - m0)));
        float p2 = __uint_as_float(f2tf(exp2f(acc[nt][2] - m1)));
        float p3 = __uint_as_float(f2tf(exp2f(acc[nt][3] - m1)));
        s0 += p0 + p1; s1 += p2 + p3;
        *(float2*)&sSw[g * STR_S + nt * 8 + 2 * c4] = make_float2(p0, p1);
        *(float2*)&sSw[(g + 8) * STR_S + nt * 8 + 2 * c4] = make_float2(p2, p3);
    }
    s0 += __shfl_xor_sync(0xffffffffu, s0, 1);
    s0 += __shfl_xor_sync(0xffffffffu, s0, 2);
    s1 += __shfl_xor_sync(0xffffffffu, s1, 1);
    s1 += __shfl_xor_sync(0xffffffffu, s1, 2);
    l0 = l0 * f0 + s0; l1 = l1 * f1 + s1;
#pragma unroll
    for (int nt = 0; nt < 4; nt++) {
        O[nt][0] *= f0; O[nt][1] *= f0; O[nt][2] *= f1; O[nt][3] *= f1;
    }
    __syncwarp();
#pragma unroll
    for (int ks = 0; ks < NTC; ks++) {
        int j = ks * 8;
        uint32_t a0 = __float_as_uint(sSw[g * STR_S + j + c4]);
        uint32_t a1 = __float_as_uint(sSw[(g + 8) * STR_S + j + c4]);
        uint32_t a2 = __float_as_uint(sSw[g * STR_S + j + c4 + 4]);
        uint32_t a3 = __float_as_uint(sSw[(g + 8) * STR_S + j + c4 + 4]);
#pragma unroll
        for (int nt = 0; nt < 4; nt++) {
            uint32_t b0 = __float_as_uint(sV[(jb + j + c4) * 40 + nt * 8 + g]);
            uint32_t b1 = __float_as_uint(sV[(jb + j + c4 + 4) * 40 + nt * 8 + g]);
            mma8(O[nt], a0, a1, a2, a3, b0, b1);
        }
    }
    __syncwarp();
}

__global__ __launch_bounds__(384)
void attn_flash() {
    extern __shared__ float s[];
    float* sK = s;
    float* sV = s + SV_OFF;
    float* sQ = s + SQ_OFF;

    const int tid = threadIdx.x;
    const int warp = tid >> 5, lane = tid & 31;
    float* sSw = s + SS_OFF + warp * (16 * STR_S);
    const int g = lane >> 2, c4 = lane & 3;
    const int h = blockIdx.y;
    // remap z so the 8 batches sharing one mask window are adjacent in schedule
    const int z = blockIdx.z;
    const int w = z >> 3, bat = z & 7;
    const int b = bat * NW + w;
    const size_t kvbase = (size_t)(b * NHEAD + h) * (NTOK * HD);
    const int r0 = blockIdx.x * 192;

    // fill K/V (tf32, padded row 343 = 0)
    for (int i4 = tid; i4 < 344 * 8; i4 += 384) {
        int n = i4 >> 3, d4 = (i4 & 7) << 2;
        float4 kk, vv;
        if (n < NTOK) {
            kk = *(const float4*)&g_k[kvbase + (size_t)n * HD + d4];
            vv = *(const float4*)&g_v[kvbase + (size_t)n * HD + d4];
        } else {
            kk = make_float4(0.f, 0.f, 0.f, 0.f);
            vv = kk;
        }
        sK[n * 36 + d4 + 0] = to_tf32(kk.x);
        sK[n * 36 + d4 + 1] = to_tf32(kk.y);
        sK[n * 36 + d4 + 2] = to_tf32(kk.z);
        sK[n * 36 + d4 + 3] = to_tf32(kk.w);
        sV[n * 40 + d4 + 0] = to_tf32(vv.x);
        sV[n * 40 + d4 + 1] = to_tf32(vv.y);
        sV[n * 40 + d4 + 2] = to_tf32(vv.z);
        sV[n * 40 + d4 + 3] = to_tf32(vv.w);
    }
    // fill Q tile (192 rows, coalesced)
    for (int i4 = tid; i4 < 192 * 8; i4 += 384) {
        int i = i4 >> 3, d4 = (i4 & 7) << 2;
        int r = r0 + i;
        float4 q = (r < NTOK) ? *(const float4*)&g_q[kvbase + (size_t)r * HD + d4]
                              : make_float4(0.f, 0.f, 0.f, 0.f);
        sQ[i * 36 + d4 + 0] = to_tf32(q.x);
        sQ[i * 36 + d4 + 1] = to_tf32(q.y);
        sQ[i * 36 + d4 + 2] = to_tf32(q.z);
        sQ[i * 36 + d4 + 3] = to_tf32(q.w);
    }
    __syncthreads();

    const int qrow0 = r0 + warp * 16;
    if (qrow0 >= NTOK) return;

    const int ra = qrow0 + g, rb = ra + 8;
    const int rca = (ra < NTOK) ? ra : 0;
    const int rcb = (rb < NTOK) ? rb : 0;

    // Q fragments from smem (conflict-free)
    uint32_t aQ[4][4];
    {
        int lr = warp * 16 + g;
#pragma unroll
        for (int ks = 0; ks < 4; ks++) {
            aQ[ks][0] = __float_as_uint(sQ[lr * 36 + ks * 8 + c4]);
            aQ[ks][1] = __float_as_uint(sQ[(lr + 8) * 36 + ks * 8 + c4]);
            aQ[ks][2] = __float_as_uint(sQ[lr * 36 + ks * 8 + c4 + 4]);
            aQ[ks][3] = __float_as_uint(sQ[(lr + 8) * 36 + ks * 8 + c4 + 4]);
        }
    }
    const float* bm0 = g_bm + (size_t)((w * NHEAD + h) * NTOK) * BMSTR;
    const float* bmA = bm0 + (size_t)rca * BMSTR;
    const float* bmB = bm0 + (size_t)rcb * BMSTR;

    float O[4][4] = {};
    float m0 = -1e30f, m1 = -1e30f, l0 = 0.f, l1 = 0.f;

#pragma unroll 1
    for (int jb = 0; jb < 320; jb += 64)
        flash_chunk<8>(jb, sK, sV, sSw, aQ, O, m0, m1, l0, l1, bmA, bmB, g, c4);
    flash_chunk<3>(320, sK, sV, sSw, aQ, O, m0, m1, l0, l1, bmA, bmB, g, c4);

    const float i0 = 1.f / l0, i1 = 1.f / l1;
#pragma unroll
    for (int nt = 0; nt < 4; nt++) {
        int dc = h * HD + nt * 8 + 2 * c4;
        if (ra < NTOK)
            *(float2*)&g_att[((size_t)b * NTOK + ra) * DIM + dc] =
                make_float2(O[nt][0] * i0, O[nt][1] * i0);
        if (rb < NTOK)
            *(float2*)&g_att[((size_t)b * NTOK + rb) * DIM + dc] =
                make_float2(O[nt][2] * i1, O[nt][3] * i1);
    }
}

// ---------------- launch ----------------
extern "C" void kernel_launch(void* const* d_in, const int* in_sizes, int n_in,
                              void* d_out, int out_size) {
    const float* x      = (const float*)d_in[0];
    const float* mask   = (const float*)d_in[1];
    const float* qkv_w  = (const float*)d_in[2];
    const float* qkv_b  = (const float*)d_in[3];
    const float* proj_w = (const float*)d_in[4];
    const float* proj_b = (const float*)d_in[5];
    const float* rpb    = (const float*)d_in[6];
    const int*   rel    = (const int*)d_in[7];
    float* out = (float*)d_out;

    const int gemm_smem = (6400 + 9600) * 4;   // 64,000 B -> 3 CTAs/SM
    cudaFuncSetAttribute(gemm_tc<0>, cudaFuncAttributeMaxDynamicSharedMemorySize, gemm_smem);
    cudaFuncSetAttribute(gemm_tc<1>, cudaFuncAttributeMaxDynamicSharedMemorySize, gemm_smem);
    cudaFuncSetAttribute(attn_flash, cudaFuncAttributeMaxDynamicSharedMemorySize, FL_SMEM_BYTES);

    {
        const int total = NW * NHEAD * NTOK * BMSTR;
        bm_kernel<<<(total + 255) / 256, 256>>>(mask, rpb, rel);
    }
    gemm_tc<1><<<dim3(MROWS / 64, 3), 256, gemm_smem>>>(x, qkv_w, qkv_b, nullptr);
    attn_flash<<<dim3(2, NHEAD, BWIN), 384, FL_SMEM_BYTES>>>();
    gemm_tc<0><<<dim3(MROWS / 64, 1), 256, gemm_smem>>>(nullptr, proj_w, proj_b, out);
}

// round 9
// speedup vs baseline: 7.4068x; 1.7692x over previous
#include <cuda_runtime.h>
#include <cuda_fp16.h>
#include <cuda_bf16.h>
#include <cstdint>

// Problem constants
#define BWIN   512
#define NTOK   343
#define DIM    96
#define NHEAD  3
#define HD     32
#define NW     64
#define MROWS  (BWIN * NTOK)  // 175616
#define LOG2E  1.4426950408889634f
#define QSCALE (0.17677669529663687f * LOG2E)
#define BMSTR  344

// ---------------- device scratch (half precision intermediates) ----------------
__device__ __half g_q[BWIN * NHEAD * NTOK * HD];
__device__ __half g_k[BWIN * NHEAD * NTOK * HD];
__device__ __half g_v[BWIN * NHEAD * NTOK * HD];
__device__ __half g_att[BWIN * NTOK * DIM];
__device__ float  g_bm[NW * NHEAD * NTOK * BMSTR];   // (mask + rpb) * log2e, padded

// ---------------- helpers ----------------
__device__ __forceinline__ float ex2(float x) {
    float y; asm("ex2.approx.ftz.f32 %0, %1;" : "=f"(y) : "f"(x)); return y;
}
__device__ __forceinline__ uint32_t pack2(float lo, float hi) {
    uint32_t r; asm("cvt.rn.f16x2.f32 %0, %1, %2;" : "=r"(r) : "f"(hi), "f"(lo)); return r;
}
// D += A(16x16 f16 row) * B(16x8 f16 col), fp32 accum
__device__ __forceinline__ void mma16(float* c, uint32_t a0, uint32_t a1, uint32_t a2, uint32_t a3,
                                      uint32_t b0, uint32_t b1) {
    asm volatile("mma.sync.aligned.m16n8k16.row.col.f32.f16.f16.f32 "
                 "{%0,%1,%2,%3}, {%4,%5,%6,%7}, {%8,%9}, {%0,%1,%2,%3};\n"
                 : "+f"(c[0]), "+f"(c[1]), "+f"(c[2]), "+f"(c[3])
                 : "r"(a0), "r"(a1), "r"(a2), "r"(a3), "r"(b0), "r"(b1));
}

// ---------------- kernel 0: fuse mask + rpb, scale by log2e ----------------
__global__ void bm_kernel(const float* __restrict__ mask,
                          const float* __restrict__ rpb,
                          const int*   __restrict__ rel) {
    int idx = blockIdx.x * blockDim.x + threadIdx.x;
    const int total = NW * NHEAD * NTOK * BMSTR;
    if (idx >= total) return;
    int m = idx % BMSTR;
    int t = idx / BMSTR;
    int n = t % NTOK;
    t /= NTOK;
    int h = t % NHEAD;
    int w = t / NHEAD;
    float v;
    if (m >= NTOK) v = -1e30f;
    else v = (mask[(w * NTOK + n) * NTOK + m] + rpb[rel[n * NTOK + m] * NHEAD + h]) * LOG2E;
    g_bm[idx] = v;
}

// ---------------- fp16 tensor-core GEMM ----------------
// CTA: 64 rows x (NCH*96) cols, 256 threads = 8 warps (4 m-groups x 2 n-groups).
// EPI==1 (NCH=3): qkv -> g_q/g_k/g_v (half). EPI==0 (NCH=1): proj (g_att half) -> out fp32.
#define GSTR 104   // smem row stride in halves (52 words -> conflict-free)
template <int EPI>
__global__ __launch_bounds__(256)
void gemm_fp16(const float* __restrict__ A,
               const float* __restrict__ W,
               const float* __restrict__ bias,
               float* __restrict__ out) {
    constexpr int NCH = EPI ? 3 : 1;
    extern __shared__ __half sh[];
    __half* sA = sh;                 // [64][GSTR]
    __half* sW = sh + 64 * GSTR;     // [NCH*96][GSTR]

    const int tid = threadIdx.x;
    const int m0 = blockIdx.x * 64;

    if (EPI == 1) {
        // A = x (fp32) -> half
        for (int it = tid; it < 64 * 24; it += 256) {
            int row = it / 24, k4 = (it % 24) * 4;
            float4 a = *(const float4*)&A[(size_t)(m0 + row) * 96 + k4];
            *(uint32_t*)&sA[row * GSTR + k4]     = pack2(a.x, a.y);
            *(uint32_t*)&sA[row * GSTR + k4 + 2] = pack2(a.z, a.w);
        }
    } else {
        // A = g_att (half) -> copy (12 uint4 per 96-half row)
        for (int it = tid; it < 64 * 12; it += 256) {
            int row = it / 12, k8 = (it % 12) * 8;
            *(uint4*)&sA[row * GSTR + k8] = *(const uint4*)&g_att[(size_t)(m0 + row) * 96 + k8];
        }
    }
    for (int it = tid; it < NCH * 96 * 24; it += 256) {
        int row = it / 24, k4 = (it % 24) * 4;
        float4 wv = *(const float4*)&W[(size_t)row * 96 + k4];
        *(uint32_t*)&sW[row * GSTR + k4]     = pack2(wv.x, wv.y);
        *(uint32_t*)&sW[row * GSTR + k4 + 2] = pack2(wv.z, wv.w);
    }
    __syncthreads();

    const int warp = tid >> 5, lane = tid & 31;
    const int g = lane >> 2, c4 = lane & 3;
    const int wm = warp & 3;   // 4 m-groups of 16 rows
    const int wn = warp >> 2;  // 2 n-groups of 48 cols per chunk

    float acc[NCH][6][4];
#pragma unroll
    for (int ch = 0; ch < NCH; ch++)
#pragma unroll
        for (int nt = 0; nt < 6; nt++) {
            int cc = ch * 96 + wn * 48 + nt * 8 + 2 * c4;
            float b0 = bias[cc], b1 = bias[cc + 1];
            acc[ch][nt][0] = b0; acc[ch][nt][1] = b1;
            acc[ch][nt][2] = b0; acc[ch][nt][3] = b1;
        }

#pragma unroll
    for (int ks = 0; ks < 6; ks++) {
        int kk = ks * 16 + 2 * c4;
        int r = wm * 16 + g;
        uint32_t a0 = *(const uint32_t*)&sA[r * GSTR + kk];
        uint32_t a1 = *(const uint32_t*)&sA[(r + 8) * GSTR + kk];
        uint32_t a2 = *(const uint32_t*)&sA[r * GSTR + kk + 8];
        uint32_t a3 = *(const uint32_t*)&sA[(r + 8) * GSTR + kk + 8];
#pragma unroll
        for (int ch = 0; ch < NCH; ch++)
#pragma unroll
            for (int nt = 0; nt < 6; nt++) {
                int n = ch * 96 + wn * 48 + nt * 8 + g;
                uint32_t b0 = *(const uint32_t*)&sW[n * GSTR + kk];
                uint32_t b1 = *(const uint32_t*)&sW[n * GSTR + kk + 8];
                mma16(acc[ch][nt], a0, a1, a2, a3, b0, b1);
            }
    }

    int ra = m0 + wm * 16 + g;
    int rb = ra + 8;
    if (EPI == 0) {
#pragma unroll
        for (int nt = 0; nt < 6; nt++) {
            int cc = wn * 48 + nt * 8 + 2 * c4;
            *(float2*)&out[(size_t)ra * 96 + cc] = make_float2(acc[0][nt][0], acc[0][nt][1]);
            *(float2*)&out[(size_t)rb * 96 + cc] = make_float2(acc[0][nt][2], acc[0][nt][3]);
        }
    } else {
        int ba = ra / NTOK, ta = ra - ba * NTOK;
        int bb = rb / NTOK, tb = rb - bb * NTOK;
#pragma unroll
        for (int ch = 0; ch < NCH; ch++) {
            __half* dst = (ch == 0) ? g_q : (ch == 1) ? g_k : g_v;
            const float sc = (ch == 0) ? QSCALE : 1.0f;
#pragma unroll
            for (int nt = 0; nt < 6; nt++) {
                int cc = wn * 48 + nt * 8 + 2 * c4;
                int hh = cc >> 5, dd = cc & 31;
                *(uint32_t*)&dst[((size_t)(ba * NHEAD + hh) * NTOK + ta) * HD + dd] =
                    pack2(acc[ch][nt][0] * sc, acc[ch][nt][1] * sc);
                *(uint32_t*)&dst[((size_t)(bb * NHEAD + hh) * NTOK + tb) * HD + dd] =
                    pack2(acc[ch][nt][2] * sc, acc[ch][nt][3] * sc);
            }
        }
    }
}

// ---------------- flash attention, fp16 MMAs, register-local P relayout ----------------
// smem halves: sK [344][40]=13760, sVt [32][360]=11520, sQ [192][40]=7680 -> 65,920 B
#define SK_STR  40
#define SV_STR  360
#define SVT_OFF 13760
#define SQ_OFF  25280
#define FL_SMEM_BYTES ((SQ_OFF + 192 * SK_STR) * 2)

template <int NTC>
__device__ __forceinline__ void flash_chunk(
    int jb, const __half* __restrict__ sK, const __half* __restrict__ sVt,
    const uint32_t aQ[2][4], float O[4][4],
    float& m0, float& m1, float& l0, float& l1,
    const float* __restrict__ bmA, const float* __restrict__ bmB,
    int g, int c4)
{
    // S = Q K^T + bias (bias preloaded straight into accumulators)
    float acc[NTC][4];
#pragma unroll
    for (int nt = 0; nt < NTC; nt++) {
        int c0 = jb + nt * 8 + 2 * c4;
        float2 bA = *(const float2*)&bmA[c0];
        float2 bB = *(const float2*)&bmB[c0];
        acc[nt][0] = bA.x; acc[nt][1] = bA.y;
        acc[nt][2] = bB.x; acc[nt][3] = bB.y;
    }
#pragma unroll
    for (int nt = 0; nt < NTC; nt++) {
        const __half* krow = &sK[(jb + nt * 8 + g) * SK_STR];
        uint32_t b0 = *(const uint32_t*)&krow[2 * c4];
        uint32_t b1 = *(const uint32_t*)&krow[2 * c4 + 8];
        mma16(acc[nt], aQ[0][0], aQ[0][1], aQ[0][2], aQ[0][3], b0, b1);
        uint32_t b2 = *(const uint32_t*)&krow[16 + 2 * c4];
        uint32_t b3 = *(const uint32_t*)&krow[16 + 2 * c4 + 8];
        mma16(acc[nt], aQ[1][0], aQ[1][1], aQ[1][2], aQ[1][3], b2, b3);
    }
    // chunk row max + rescale
    float cm0 = -1e30f, cm1 = -1e30f;
#pragma unroll
    for (int nt = 0; nt < NTC; nt++) {
        cm0 = fmaxf(cm0, fmaxf(acc[nt][0], acc[nt][1]));
        cm1 = fmaxf(cm1, fmaxf(acc[nt][2], acc[nt][3]));
    }
    cm0 = fmaxf(cm0, __shfl_xor_sync(0xffffffffu, cm0, 1));
    cm0 = fmaxf(cm0, __shfl_xor_sync(0xffffffffu, cm0, 2));
    cm1 = fmaxf(cm1, __shfl_xor_sync(0xffffffffu, cm1, 1));
    cm1 = fmaxf(cm1, __shfl_xor_sync(0xffffffffu, cm1, 2));
    float mn0 = fmaxf(m0, cm0), mn1 = fmaxf(m1, cm1);
    float f0 = ex2(m0 - mn0), f1 = ex2(m1 - mn1);
    m0 = mn0; m1 = mn1;
#pragma unroll
    for (int nt = 0; nt < 4; nt++) {
        O[nt][0] *= f0; O[nt][1] *= f0; O[nt][2] *= f1; O[nt][3] *= f1;
    }
    // exp + pack directly into PV A-fragments (register-local, no smem)
    constexpr int NS = (NTC + 1) / 2;
    float s0 = 0.f, s1 = 0.f;
#pragma unroll
    for (int s = 0; s < NS; s++) {
        int t0 = 2 * s, t1 = 2 * s + 1;
        float e00 = ex2(acc[t0][0] - m0), e01 = ex2(acc[t0][1] - m0);
        float e02 = ex2(acc[t0][2] - m1), e03 = ex2(acc[t0][3] - m1);
        uint32_t a0 = pack2(e00, e01);
        uint32_t a1 = pack2(e02, e03);
        uint32_t a2 = 0, a3 = 0;
        s0 += e00 + e01; s1 += e02 + e03;
        if (t1 < NTC) {
            float e10 = ex2(acc[t1][0] - m0), e11 = ex2(acc[t1][1] - m0);
            float e12 = ex2(acc[t1][2] - m1), e13 = ex2(acc[t1][3] - m1);
            a2 = pack2(e10, e11);
            a3 = pack2(e12, e13);
            s0 += e10 + e11; s1 += e12 + e13;
        }
        int kk = jb + s * 16 + 2 * c4;
#pragma unroll
        for (int nt = 0; nt < 4; nt++) {
            const __half* vrow = &sVt[(nt * 8 + g) * SV_STR];
            uint32_t b0 = *(const uint32_t*)&vrow[kk];
            uint32_t b1 = *(const uint32_t*)&vrow[kk + 8];
            mma16(O[nt], a0, a1, a2, a3, b0, b1);
        }
    }
    s0 += __shfl_xor_sync(0xffffffffu, s0, 1);
    s0 += __shfl_xor_sync(0xffffffffu, s0, 2);
    s1 += __shfl_xor_sync(0xffffffffu, s1, 1);
    s1 += __shfl_xor_sync(0xffffffffu, s1, 2);
    l0 = l0 * f0 + s0; l1 = l1 * f1 + s1;
}

__global__ __launch_bounds__(384, 2)
void attn_flash() {
    extern __shared__ __half sh[];
    __half* sK  = sh;
    __half* sVt = sh + SVT_OFF;
    __half* sQ  = sh + SQ_OFF;

    const int tid = threadIdx.x;
    const int warp = tid >> 5, lane = tid & 31;
    const int g = lane >> 2, c4 = lane & 3;
    const int h = blockIdx.y;
    const int z = blockIdx.z;
    const int w = z >> 3, bat = z & 7;      // batches sharing one mask window adjacent
    const int b = bat * NW + w;
    const size_t kvbase = (size_t)(b * NHEAD + h) * (NTOK * HD);
    const int r0 = blockIdx.x * 192;

    // K fill: 4 uint4 (8 halves each) per 32-half row; row 343 zeroed
    for (int i = tid; i < 344 * 4; i += 384) {
        int n = i >> 2, q = (i & 3) * 8;
        uint4 val = (n < NTOK) ? *(const uint4*)&g_k[kvbase + (size_t)n * HD + q]
                               : make_uint4(0u, 0u, 0u, 0u);
        *(uint4*)&sK[n * SK_STR + q] = val;
    }
    // V fill transposed: sVt[d][n]
    for (int i = tid; i < NTOK * 16; i += 384) {
        int n = i / 16, dp = (i % 16) * 2;
        __half2 v = *(const __half2*)&g_v[kvbase + (size_t)n * HD + dp];
        sVt[dp * SV_STR + n] = __low2half(v);
        sVt[(dp + 1) * SV_STR + n] = __high2half(v);
    }
    // zero V cols 343..359 (padding touched by last k-step)
    for (int i = tid; i < 32 * 17; i += 384) {
        int d = i / 17, j = 343 + (i % 17);
        sVt[d * SV_STR + j] = __ushort_as_half(0);
    }
    // Q fill: 4 uint4 per 32-half row
    for (int i = tid; i < 192 * 4; i += 384) {
        int n = i >> 2, q = (i & 3) * 8;
        int r = r0 + n;
        uint4 val = (r < NTOK) ? *(const uint4*)&g_q[kvbase + (size_t)r * HD + q]
                               : make_uint4(0u, 0u, 0u, 0u);
        *(uint4*)&sQ[n * SK_STR + q] = val;
    }
    __syncthreads();

    const int qrow0 = r0 + warp * 16;
    if (qrow0 >= NTOK) return;   // dead warps: no CTA syncs remain

    const int ra = qrow0 + g, rb = ra + 8;
    const int rca = (ra < NTOK) ? ra : 0;
    const int rcb = (rb < NTOK) ? rb : 0;

    // Q fragments (2 k16-steps)
    uint32_t aQ[2][4];
    {
        int lr = warp * 16 + g;
#pragma unroll
        for (int ks = 0; ks < 2; ks++) {
            int kk = ks * 16 + 2 * c4;
            aQ[ks][0] = *(const uint32_t*)&sQ[lr * SK_STR + kk];
            aQ[ks][1] = *(const uint32_t*)&sQ[(lr + 8) * SK_STR + kk];
            aQ[ks][2] = *(const uint32_t*)&sQ[lr * SK_STR + kk + 8];
            aQ[ks][3] = *(const uint32_t*)&sQ[(lr + 8) * SK_STR + kk + 8];
        }
    }
    const float* bm0 = g_bm + (size_t)((w * NHEAD + h) * NTOK) * BMSTR;
    const float* bmA = bm0 + (size_t)rca * BMSTR;
    const float* bmB = bm0 + (size_t)rcb * BMSTR;

    float O[4][4] = {};
    float m0 = -1e30f, m1 = -1e30f, l0 = 0.f, l1 = 0.f;

#pragma unroll 1
    for (int jb = 0; jb < 320; jb += 64)
        flash_chunk<8>(jb, sK, sVt, aQ, O, m0, m1, l0, l1, bmA, bmB, g, c4);
    flash_chunk<3>(320, sK, sVt, aQ, O, m0, m1, l0, l1, bmA, bmB, g, c4);

    const float i0 = 1.f / l0, i1 = 1.f / l1;
#pragma unroll
    for (int nt = 0; nt < 4; nt++) {
        int dc = h * HD + nt * 8 + 2 * c4;
        if (ra < NTOK)
            *(uint32_t*)&g_att[((size_t)b * NTOK + ra) * DIM + dc] =
                pack2(O[nt][0] * i0, O[nt][1] * i0);
        if (rb < NTOK)
            *(uint32_t*)&g_att[((size_t)b * NTOK + rb) * DIM + dc] =
                pack2(O[nt][2] * i1, O[nt][3] * i1);
    }
}

// ---------------- launch ----------------
extern "C" void kernel_launch(void* const* d_in, const int* in_sizes, int n_in,
                              void* d_out, int out_size) {
    const float* x      = (const float*)d_in[0];
    const float* mask   = (const float*)d_in[1];
    const float* qkv_w  = (const float*)d_in[2];
    const float* qkv_b  = (const float*)d_in[3];
    const float* proj_w = (const float*)d_in[4];
    const float* proj_b = (const float*)d_in[5];
    const float* rpb    = (const float*)d_in[6];
    const int*   rel    = (const int*)d_in[7];
    float* out = (float*)d_out;

    const int qkv_smem  = (64 + 288) * GSTR * 2;   // 73,216 B
    const int proj_smem = (64 + 96) * GSTR * 2;    // 33,280 B
    cudaFuncSetAttribute(gemm_fp16<1>, cudaFuncAttributeMaxDynamicSharedMemorySize, qkv_smem);
    cudaFuncSetAttribute(gemm_fp16<0>, cudaFuncAttributeMaxDynamicSharedMemorySize, proj_smem);
    cudaFuncSetAttribute(attn_flash, cudaFuncAttributeMaxDynamicSharedMemorySize, FL_SMEM_BYTES);

    {
        const int total = NW * NHEAD * NTOK * BMSTR;
        bm_kernel<<<(total + 255) / 256, 256>>>(mask, rpb, rel);
    }
    gemm_fp16<1><<<MROWS / 64, 256, qkv_smem>>>(x, qkv_w, qkv_b, nullptr);
    attn_flash<<<dim3(2, NHEAD, BWIN), 384, FL_SMEM_BYTES>>>();
    gemm_fp16<0><<<MROWS / 64, 256, proj_smem>>>(nullptr, proj_w, proj_b, out);
}

// round 10
// speedup vs baseline: 8.3316x; 1.1249x over previous
#include <cuda_runtime.h>
#include <cuda_fp16.h>
#include <cuda_bf16.h>
#include <cstdint>

// Problem constants
#define BWIN   512
#define NTOK   343
#define DIM    96
#define NHEAD  3
#define HD     32
#define NW     64
#define MROWS  (BWIN * NTOK)  // 175616
#define LOG2E  1.4426950408889634f
#define QSCALE (0.17677669529663687f * LOG2E)
#define BMSTR  344

// ---------------- device scratch (half precision intermediates) ----------------
__device__ __half g_q[BWIN * NHEAD * NTOK * HD];
__device__ __half g_k[BWIN * NHEAD * NTOK * HD];
__device__ __half g_v[BWIN * NHEAD * NTOK * HD];
__device__ __half g_att[BWIN * NTOK * DIM];
__device__ __half g_bm[NW * NHEAD * NTOK * BMSTR];   // (mask + rpb) * log2e, half, padded

// ---------------- helpers ----------------
__device__ __forceinline__ float ex2(float x) {
    float y; asm("ex2.approx.ftz.f32 %0, %1;" : "=f"(y) : "f"(x)); return y;
}
__device__ __forceinline__ uint32_t pack2(float lo, float hi) {
    uint32_t r; asm("cvt.rn.f16x2.f32 %0, %1, %2;" : "=r"(r) : "f"(hi), "f"(lo)); return r;
}
// D += A(16x16 f16 row) * B(16x8 f16 col), fp32 accum
__device__ __forceinline__ void mma16(float* c, uint32_t a0, uint32_t a1, uint32_t a2, uint32_t a3,
                                      uint32_t b0, uint32_t b1) {
    asm volatile("mma.sync.aligned.m16n8k16.row.col.f32.f16.f16.f32 "
                 "{%0,%1,%2,%3}, {%4,%5,%6,%7}, {%8,%9}, {%0,%1,%2,%3};\n"
                 : "+f"(c[0]), "+f"(c[1]), "+f"(c[2]), "+f"(c[3])
                 : "r"(a0), "r"(a1), "r"(a2), "r"(a3), "r"(b0), "r"(b1));
}

// ---------------- kernel 0: fuse mask + rpb, scale by log2e, store half ----------------
__global__ void bm_kernel(const float* __restrict__ mask,
                          const float* __restrict__ rpb,
                          const int*   __restrict__ rel) {
    int idx = blockIdx.x * blockDim.x + threadIdx.x;
    const int total = NW * NHEAD * NTOK * BMSTR;
    if (idx >= total) return;
    int m = idx % BMSTR;
    int t = idx / BMSTR;
    int n = t % NTOK;
    t /= NTOK;
    int h = t % NHEAD;
    int w = t / NHEAD;
    float v;
    if (m >= NTOK) v = -60000.0f;   // ex2 -> 0
    else v = (mask[(w * NTOK + n) * NTOK + m] + rpb[rel[n * NTOK + m] * NHEAD + h]) * LOG2E;
    g_bm[idx] = __float2half(v);
}

// ---------------- fp16 tensor-core GEMM ----------------
// CTA: 64 rows x (NCH*96) cols, 256 threads = 8 warps (4 m-groups x 2 n-groups).
// EPI==1 (NCH=3): qkv -> g_q/g_k/g_v (half). EPI==0 (NCH=1): proj (g_att half) -> out fp32.
#define GSTR 104   // smem row stride in halves (52 words -> conflict-free)
template <int EPI>
__global__ __launch_bounds__(256)
void gemm_fp16(const float* __restrict__ A,
               const float* __restrict__ W,
               const float* __restrict__ bias,
               float* __restrict__ out) {
    constexpr int NCH = EPI ? 3 : 1;
    extern __shared__ __half sh[];
    __half* sA = sh;                 // [64][GSTR]
    __half* sW = sh + 64 * GSTR;     // [NCH*96][GSTR]

    const int tid = threadIdx.x;
    const int m0 = blockIdx.x * 64;

    if (EPI == 1) {
        for (int it = tid; it < 64 * 24; it += 256) {
            int row = it / 24, k4 = (it % 24) * 4;
            float4 a = *(const float4*)&A[(size_t)(m0 + row) * 96 + k4];
            *(uint32_t*)&sA[row * GSTR + k4]     = pack2(a.x, a.y);
            *(uint32_t*)&sA[row * GSTR + k4 + 2] = pack2(a.z, a.w);
        }
    } else {
        for (int it = tid; it < 64 * 12; it += 256) {
            int row = it / 12, k8 = (it % 12) * 8;
            *(uint4*)&sA[row * GSTR + k8] = *(const uint4*)&g_att[(size_t)(m0 + row) * 96 + k8];
        }
    }
    for (int it = tid; it < NCH * 96 * 24; it += 256) {
        int row = it / 24, k4 = (it % 24) * 4;
        float4 wv = *(const float4*)&W[(size_t)row * 96 + k4];
        *(uint32_t*)&sW[row * GSTR + k4]     = pack2(wv.x, wv.y);
        *(uint32_t*)&sW[row * GSTR + k4 + 2] = pack2(wv.z, wv.w);
    }
    __syncthreads();

    const int warp = tid >> 5, lane = tid & 31;
    const int g = lane >> 2, c4 = lane & 3;
    const int wm = warp & 3;
    const int wn = warp >> 2;

    float acc[NCH][6][4];
#pragma unroll
    for (int ch = 0; ch < NCH; ch++)
#pragma unroll
        for (int nt = 0; nt < 6; nt++) {
            int cc = ch * 96 + wn * 48 + nt * 8 + 2 * c4;
            float b0 = bias[cc], b1 = bias[cc + 1];
            acc[ch][nt][0] = b0; acc[ch][nt][1] = b1;
            acc[ch][nt][2] = b0; acc[ch][nt][3] = b1;
        }

#pragma unroll
    for (int ks = 0; ks < 6; ks++) {
        int kk = ks * 16 + 2 * c4;
        int r = wm * 16 + g;
        uint32_t a0 = *(const uint32_t*)&sA[r * GSTR + kk];
        uint32_t a1 = *(const uint32_t*)&sA[(r + 8) * GSTR + kk];
        uint32_t a2 = *(const uint32_t*)&sA[r * GSTR + kk + 8];
        uint32_t a3 = *(const uint32_t*)&sA[(r + 8) * GSTR + kk + 8];
#pragma unroll
        for (int ch = 0; ch < NCH; ch++)
#pragma unroll
            for (int nt = 0; nt < 6; nt++) {
                int n = ch * 96 + wn * 48 + nt * 8 + g;
                uint32_t b0 = *(const uint32_t*)&sW[n * GSTR + kk];
                uint32_t b1 = *(const uint32_t*)&sW[n * GSTR + kk + 8];
                mma16(acc[ch][nt], a0, a1, a2, a3, b0, b1);
            }
    }

    int ra = m0 + wm * 16 + g;
    int rb = ra + 8;
    if (EPI == 0) {
#pragma unroll
        for (int nt = 0; nt < 6; nt++) {
            int cc = wn * 48 + nt * 8 + 2 * c4;
            *(float2*)&out[(size_t)ra * 96 + cc] = make_float2(acc[0][nt][0], acc[0][nt][1]);
            *(float2*)&out[(size_t)rb * 96 + cc] = make_float2(acc[0][nt][2], acc[0][nt][3]);
        }
    } else {
        int ba = ra / NTOK, ta = ra - ba * NTOK;
        int bb = rb / NTOK, tb = rb - bb * NTOK;
#pragma unroll
        for (int ch = 0; ch < NCH; ch++) {
            __half* dst = (ch == 0) ? g_q : (ch == 1) ? g_k : g_v;
            const float sc = (ch == 0) ? QSCALE : 1.0f;
#pragma unroll
            for (int nt = 0; nt < 6; nt++) {
                int cc = wn * 48 + nt * 8 + 2 * c4;
                int hh = cc >> 5, dd = cc & 31;
                *(uint32_t*)&dst[((size_t)(ba * NHEAD + hh) * NTOK + ta) * HD + dd] =
                    pack2(acc[ch][nt][0] * sc, acc[ch][nt][1] * sc);
                *(uint32_t*)&dst[((size_t)(bb * NHEAD + hh) * NTOK + tb) * HD + dd] =
                    pack2(acc[ch][nt][2] * sc, acc[ch][nt][3] * sc);
            }
        }
    }
}

// ---------------- flash attention: no-max softmax (bounded logits) ----------------
// smem halves: sK [344][40]=13760, sVt [32][360]=11520, sQ [192][40]=7680 -> 65,920 B
#define SK_STR  40
#define SV_STR  360
#define SVT_OFF 13760
#define SQ_OFF  25280
#define FL_SMEM_BYTES ((SQ_OFF + 192 * SK_STR) * 2)

template <int NTC>
__device__ __forceinline__ void flash_chunk(
    int jb, const __half* __restrict__ sK, const __half* __restrict__ sVt,
    const uint32_t aQ[2][4], float O[4][4],
    float& s0, float& s1,
    const __half* __restrict__ bmA, const __half* __restrict__ bmB,
    int g, int c4)
{
    // issue bias loads first (half2) — latency hides under the MMAs below
    __half2 hA[NTC], hB[NTC];
#pragma unroll
    for (int nt = 0; nt < NTC; nt++) {
        int c0 = jb + nt * 8 + 2 * c4;
        hA[nt] = *(const __half2*)&bmA[c0];
        hB[nt] = *(const __half2*)&bmB[c0];
    }
    // S = Q K^T (from zero; bias added after)
    float acc[NTC][4];
#pragma unroll
    for (int nt = 0; nt < NTC; nt++) {
        acc[nt][0] = acc[nt][1] = acc[nt][2] = acc[nt][3] = 0.f;
        const __half* krow = &sK[(jb + nt * 8 + g) * SK_STR];
        uint32_t b0 = *(const uint32_t*)&krow[2 * c4];
        uint32_t b1 = *(const uint32_t*)&krow[2 * c4 + 8];
        mma16(acc[nt], aQ[0][0], aQ[0][1], aQ[0][2], aQ[0][3], b0, b1);
        uint32_t b2 = *(const uint32_t*)&krow[16 + 2 * c4];
        uint32_t b3 = *(const uint32_t*)&krow[16 + 2 * c4 + 8];
        mma16(acc[nt], aQ[1][0], aQ[1][1], aQ[1][2], aQ[1][3], b2, b3);
    }
    // P = ex2(S + bias), pack to PV A-fragments, accumulate row sums; O += P V
    constexpr int NS = (NTC + 1) / 2;
#pragma unroll
    for (int s = 0; s < NS; s++) {
        int t0 = 2 * s, t1 = 2 * s + 1;
        float2 fA0 = __half22float2(hA[t0]);
        float2 fB0 = __half22float2(hB[t0]);
        float e00 = ex2(acc[t0][0] + fA0.x), e01 = ex2(acc[t0][1] + fA0.y);
        float e02 = ex2(acc[t0][2] + fB0.x), e03 = ex2(acc[t0][3] + fB0.y);
        uint32_t a0 = pack2(e00, e01);
        uint32_t a1 = pack2(e02, e03);
        uint32_t a2 = 0, a3 = 0;
        s0 += e00 + e01; s1 += e02 + e03;
        if (t1 < NTC) {
            float2 fA1 = __half22float2(hA[t1]);
            float2 fB1 = __half22float2(hB[t1]);
            float e10 = ex2(acc[t1][0] + fA1.x), e11 = ex2(acc[t1][1] + fA1.y);
            float e12 = ex2(acc[t1][2] + fB1.x), e13 = ex2(acc[t1][3] + fB1.y);
            a2 = pack2(e10, e11);
            a3 = pack2(e12, e13);
            s0 += e10 + e11; s1 += e12 + e13;
        }
        int kk = jb + s * 16 + 2 * c4;
#pragma unroll
        for (int nt = 0; nt < 4; nt++) {
            const __half* vrow = &sVt[(nt * 8 + g) * SV_STR];
            uint32_t b0 = *(const uint32_t*)&vrow[kk];
            uint32_t b1 = *(const uint32_t*)&vrow[kk + 8];
            mma16(O[nt], a0, a1, a2, a3, b0, b1);
        }
    }
}

__global__ __launch_bounds__(384, 2)
void attn_flash() {
    extern __shared__ __half sh[];
    __half* sK  = sh;
    __half* sVt = sh + SVT_OFF;
    __half* sQ  = sh + SQ_OFF;

    const int tid = threadIdx.x;
    const int warp = tid >> 5, lane = tid & 31;
    const int g = lane >> 2, c4 = lane & 3;
    const int h = blockIdx.y;
    const int z = blockIdx.z;
    const int w = z >> 3, bat = z & 7;      // batches sharing one mask window adjacent
    const int b = bat * NW + w;
    const size_t kvbase = (size_t)(b * NHEAD + h) * (NTOK * HD);
    const int r0 = blockIdx.x * 192;

    // K fill: 4 uint4 (8 halves) per 32-half row; row 343 zeroed
    for (int i = tid; i < 344 * 4; i += 384) {
        int n = i >> 2, q = (i & 3) * 8;
        uint4 val = (n < NTOK) ? *(const uint4*)&g_k[kvbase + (size_t)n * HD + q]
                               : make_uint4(0u, 0u, 0u, 0u);
        *(uint4*)&sK[n * SK_STR + q] = val;
    }
    // V fill transposed: sVt[d][n]
    for (int i = tid; i < NTOK * 16; i += 384) {
        int n = i / 16, dp = (i % 16) * 2;
        __half2 v = *(const __half2*)&g_v[kvbase + (size_t)n * HD + dp];
        sVt[dp * SV_STR + n] = __low2half(v);
        sVt[(dp + 1) * SV_STR + n] = __high2half(v);
    }
    // zero V cols 343..359
    for (int i = tid; i < 32 * 17; i += 384) {
        int d = i / 17, j = 343 + (i % 17);
        sVt[d * SV_STR + j] = __ushort_as_half(0);
    }
    // Q fill
    for (int i = tid; i < 192 * 4; i += 384) {
        int n = i >> 2, q = (i & 3) * 8;
        int r = r0 + n;
        uint4 val = (r < NTOK) ? *(const uint4*)&g_q[kvbase + (size_t)r * HD + q]
                               : make_uint4(0u, 0u, 0u, 0u);
        *(uint4*)&sQ[n * SK_STR + q] = val;
    }
    __syncthreads();

    const int qrow0 = r0 + warp * 16;
    if (qrow0 >= NTOK) return;   // dead warps: no CTA syncs remain

    const int ra = qrow0 + g, rb = ra + 8;
    const int rca = (ra < NTOK) ? ra : 0;
    const int rcb = (rb < NTOK) ? rb : 0;

    // Q fragments (2 k16-steps)
    uint32_t aQ[2][4];
    {
        int lr = warp * 16 + g;
#pragma unroll
        for (int ks = 0; ks < 2; ks++) {
            int kk = ks * 16 + 2 * c4;
            aQ[ks][0] = *(const uint32_t*)&sQ[lr * SK_STR + kk];
            aQ[ks][1] = *(const uint32_t*)&sQ[(lr + 8) * SK_STR + kk];
            aQ[ks][2] = *(const uint32_t*)&sQ[lr * SK_STR + kk + 8];
            aQ[ks][3] = *(const uint32_t*)&sQ[(lr + 8) * SK_STR + kk + 8];
        }
    }
    const __half* bm0 = g_bm + (size_t)((w * NHEAD + h) * NTOK) * BMSTR;
    const __half* bmA = bm0 + (size_t)rca * BMSTR;
    const __half* bmB = bm0 + (size_t)rcb * BMSTR;

    float O[4][4] = {};
    float s0 = 0.f, s1 = 0.f;

#pragma unroll 1
    for (int jb = 0; jb < 320; jb += 64)
        flash_chunk<8>(jb, sK, sVt, aQ, O, s0, s1, bmA, bmB, g, c4);
    flash_chunk<3>(320, sK, sVt, aQ, O, s0, s1, bmA, bmB, g, c4);

    // single row-sum reduce at the end
    s0 += __shfl_xor_sync(0xffffffffu, s0, 1);
    s0 += __shfl_xor_sync(0xffffffffu, s0, 2);
    s1 += __shfl_xor_sync(0xffffffffu, s1, 1);
    s1 += __shfl_xor_sync(0xffffffffu, s1, 2);
    const float i0 = 1.f / s0, i1 = 1.f / s1;

#pragma unroll
    for (int nt = 0; nt < 4; nt++) {
        int dc = h * HD + nt * 8 + 2 * c4;
        if (ra < NTOK)
            *(uint32_t*)&g_att[((size_t)b * NTOK + ra) * DIM + dc] =
                pack2(O[nt][0] * i0, O[nt][1] * i0);
        if (rb < NTOK)
            *(uint32_t*)&g_att[((size_t)b * NTOK + rb) * DIM + dc] =
                pack2(O[nt][2] * i1, O[nt][3] * i1);
    }
}

// ---------------- launch ----------------
extern "C" void kernel_launch(void* const* d_in, const int* in_sizes, int n_in,
                              void* d_out, int out_size) {
    const float* x      = (const float*)d_in[0];
    const float* mask   = (const float*)d_in[1];
    const float* qkv_w  = (const float*)d_in[2];
    const float* qkv_b  = (const float*)d_in[3];
    const float* proj_w = (const float*)d_in[4];
    const float* proj_b = (const float*)d_in[5];
    const float* rpb    = (const float*)d_in[6];
    const int*   rel    = (const int*)d_in[7];
    float* out = (float*)d_out;

    const int qkv_smem  = (64 + 288) * GSTR * 2;   // 73,216 B
    const int proj_smem = (64 + 96) * GSTR * 2;    // 33,280 B
    cudaFuncSetAttribute(gemm_fp16<1>, cudaFuncAttributeMaxDynamicSharedMemorySize, qkv_smem);
    cudaFuncSetAttribute(gemm_fp16<0>, cudaFuncAttributeMaxDynamicSharedMemorySize, proj_smem);
    cudaFuncSetAttribute(attn_flash, cudaFuncAttributeMaxDynamicSharedMemorySize, FL_SMEM_BYTES);

    {
        const int total = NW * NHEAD * NTOK * BMSTR;
        bm_kernel<<<(total + 255) / 256, 256>>>(mask, rpb, rel);
    }
    gemm_fp16<1><<<MROWS / 64, 256, qkv_smem>>>(x, qkv_w, qkv_b, nullptr);
    attn_flash<<<dim3(2, NHEAD, BWIN), 384, FL_SMEM_BYTES>>>();
    gemm_fp16<0><<<MROWS / 64, 256, proj_smem>>>(nullptr, proj_w, proj_b, out);
}

// round 11
// speedup vs baseline: 9.3810x; 1.1260x over previous
#include <cuda_runtime.h>
#include <cuda_fp16.h>
#include <cuda_bf16.h>
#include <cstdint>

// Problem constants
#define BWIN   512
#define NTOK   343
#define DIM    96
#define NHEAD  3
#define HD     32
#define NW     64
#define MROWS  (BWIN * NTOK)  // 175616
#define LOG2E  1.4426950408889634f
#define QSCALE (0.17677669529663687f * LOG2E)
#define RBLK   44     // row blocks of 8 (352 padded rows)
#define CPAIR  172    // column pairs (344 padded cols)

// ---------------- device scratch ----------------
__device__ __half g_q[BWIN * NHEAD * NTOK * HD];
__device__ __half g_k[BWIN * NHEAD * NTOK * HD];
__device__ __half g_v[BWIN * NHEAD * NTOK * HD];
__device__ __half g_att[BWIN * NTOK * DIM];
// bias in fragment order: [w*3+h][rowblk][colpair][row%8][2], half
__device__ __half g_bm[NW * NHEAD * RBLK * CPAIR * 16];

// ---------------- helpers ----------------
__device__ __forceinline__ uint32_t pack2(float lo, float hi) {
    uint32_t r; asm("cvt.rn.f16x2.f32 %0, %1, %2;" : "=r"(r) : "f"(hi), "f"(lo)); return r;
}
__device__ __forceinline__ uint32_t hadd2(uint32_t a, uint32_t b) {
    uint32_t r; asm("add.rn.f16x2 %0, %1, %2;" : "=r"(r) : "r"(a), "r"(b)); return r;
}
__device__ __forceinline__ uint32_t hex2(uint32_t a) {
    uint32_t r; asm("ex2.approx.f16x2 %0, %1;" : "=r"(r) : "r"(a)); return r;
}
__device__ __forceinline__ void mma16(float* c, uint32_t a0, uint32_t a1, uint32_t a2, uint32_t a3,
                                      uint32_t b0, uint32_t b1) {
    asm volatile("mma.sync.aligned.m16n8k16.row.col.f32.f16.f16.f32 "
                 "{%0,%1,%2,%3}, {%4,%5,%6,%7}, {%8,%9}, {%0,%1,%2,%3};\n"
                 : "+f"(c[0]), "+f"(c[1]), "+f"(c[2]), "+f"(c[3])
                 : "r"(a0), "r"(a1), "r"(a2), "r"(a3), "r"(b0), "r"(b1));
}
__device__ __forceinline__ void ldsm4(uint32_t& r0, uint32_t& r1, uint32_t& r2, uint32_t& r3,
                                      uint32_t addr) {
    asm volatile("ldmatrix.sync.aligned.m8n8.x4.shared.b16 {%0,%1,%2,%3}, [%4];"
                 : "=r"(r0), "=r"(r1), "=r"(r2), "=r"(r3) : "r"(addr));
}
__device__ __forceinline__ uint32_t smem_u32(const void* p) {
    return (uint32_t)__cvta_generic_to_shared(p);
}
#define ONES2 0x3C003C00u

// ---------------- kernel 0: fused bias in fragment order ----------------
__global__ void bm_kernel(const float* __restrict__ mask,
                          const float* __restrict__ rpb,
                          const int*   __restrict__ rel) {
    int idx = blockIdx.x * blockDim.x + threadIdx.x;
    const int total = NW * NHEAD * RBLK * CPAIR * 8;   // half2 units
    if (idx >= total) return;
    int p = idx;
    int r8 = p & 7; p >>= 3;
    int cp = p % CPAIR; p /= CPAIR;
    int rb = p % RBLK; p /= RBLK;
    int h = p % NHEAD; int w = p / NHEAD;
    int row = rb * 8 + r8;
    float v[2];
#pragma unroll
    for (int i = 0; i < 2; i++) {
        int col = cp * 2 + i;
        if (row < NTOK && col < NTOK)
            v[i] = (mask[(w * NTOK + row) * NTOK + col] + rpb[rel[row * NTOK + col] * NHEAD + h]) * LOG2E;
        else
            v[i] = -60000.0f;
    }
    *(uint32_t*)&g_bm[(size_t)idx * 2] = pack2(v[0], v[1]);
}

// ---------------- fp16 tensor-core GEMM (unchanged from R9) ----------------
#define GSTR 104
template <int EPI>
__global__ __launch_bounds__(256)
void gemm_fp16(const float* __restrict__ A,
               const float* __restrict__ W,
               const float* __restrict__ bias,
               float* __restrict__ out) {
    constexpr int NCH = EPI ? 3 : 1;
    extern __shared__ __half sh[];
    __half* sA = sh;
    __half* sW = sh + 64 * GSTR;

    const int tid = threadIdx.x;
    const int m0 = blockIdx.x * 64;

    if (EPI == 1) {
        for (int it = tid; it < 64 * 24; it += 256) {
            int row = it / 24, k4 = (it % 24) * 4;
            float4 a = *(const float4*)&A[(size_t)(m0 + row) * 96 + k4];
            *(uint32_t*)&sA[row * GSTR + k4]     = pack2(a.x, a.y);
            *(uint32_t*)&sA[row * GSTR + k4 + 2] = pack2(a.z, a.w);
        }
    } else {
        for (int it = tid; it < 64 * 12; it += 256) {
            int row = it / 12, k8 = (it % 12) * 8;
            *(uint4*)&sA[row * GSTR + k8] = *(const uint4*)&g_att[(size_t)(m0 + row) * 96 + k8];
        }
    }
    for (int it = tid; it < NCH * 96 * 24; it += 256) {
        int row = it / 24, k4 = (it % 24) * 4;
        float4 wv = *(const float4*)&W[(size_t)row * 96 + k4];
        *(uint32_t*)&sW[row * GSTR + k4]     = pack2(wv.x, wv.y);
        *(uint32_t*)&sW[row * GSTR + k4 + 2] = pack2(wv.z, wv.w);
    }
    __syncthreads();

    const int warp = tid >> 5, lane = tid & 31;
    const int g = lane >> 2, c4 = lane & 3;
    const int wm = warp & 3;
    const int wn = warp >> 2;

    float acc[NCH][6][4];
#pragma unroll
    for (int ch = 0; ch < NCH; ch++)
#pragma unroll
        for (int nt = 0; nt < 6; nt++) {
            int cc = ch * 96 + wn * 48 + nt * 8 + 2 * c4;
            float b0 = bias[cc], b1 = bias[cc + 1];
            acc[ch][nt][0] = b0; acc[ch][nt][1] = b1;
            acc[ch][nt][2] = b0; acc[ch][nt][3] = b1;
        }

#pragma unroll
    for (int ks = 0; ks < 6; ks++) {
        int kk = ks * 16 + 2 * c4;
        int r = wm * 16 + g;
        uint32_t a0 = *(const uint32_t*)&sA[r * GSTR + kk];
        uint32_t a1 = *(const uint32_t*)&sA[(r + 8) * GSTR + kk];
        uint32_t a2 = *(const uint32_t*)&sA[r * GSTR + kk + 8];
        uint32_t a3 = *(const uint32_t*)&sA[(r + 8) * GSTR + kk + 8];
#pragma unroll
        for (int ch = 0; ch < NCH; ch++)
#pragma unroll
            for (int nt = 0; nt < 6; nt++) {
                int n = ch * 96 + wn * 48 + nt * 8 + g;
                uint32_t b0 = *(const uint32_t*)&sW[n * GSTR + kk];
                uint32_t b1 = *(const uint32_t*)&sW[n * GSTR + kk + 8];
                mma16(acc[ch][nt], a0, a1, a2, a3, b0, b1);
            }
    }

    int ra = m0 + wm * 16 + g;
    int rb = ra + 8;
    if (EPI == 0) {
#pragma unroll
        for (int nt = 0; nt < 6; nt++) {
            int cc = wn * 48 + nt * 8 + 2 * c4;
            *(float2*)&out[(size_t)ra * 96 + cc] = make_float2(acc[0][nt][0], acc[0][nt][1]);
            *(float2*)&out[(size_t)rb * 96 + cc] = make_float2(acc[0][nt][2], acc[0][nt][3]);
        }
    } else {
        int ba = ra / NTOK, ta = ra - ba * NTOK;
        int bb = rb / NTOK, tb = rb - bb * NTOK;
#pragma unroll
        for (int ch = 0; ch < NCH; ch++) {
            __half* dst = (ch == 0) ? g_q : (ch == 1) ? g_k : g_v;
            const float sc = (ch == 0) ? QSCALE : 1.0f;
#pragma unroll
            for (int nt = 0; nt < 6; nt++) {
                int cc = wn * 48 + nt * 8 + 2 * c4;
                int hh = cc >> 5, dd = cc & 31;
                *(uint32_t*)&dst[((size_t)(ba * NHEAD + hh) * NTOK + ta) * HD + dd] =
                    pack2(acc[ch][nt][0] * sc, acc[ch][nt][1] * sc);
                *(uint32_t*)&dst[((size_t)(bb * NHEAD + hh) * NTOK + tb) * HD + dd] =
                    pack2(acc[ch][nt][2] * sc, acc[ch][nt][3] * sc);
            }
        }
    }
}

// ---------------- flash attention: LDSM + f16x2 softmax + ones-MMA sums ----------------
#define SK_STR  40
#define SV_STR  360
#define SVT_OFF 13760
#define SQ_OFF  25280
#define FL_SMEM_BYTES ((SQ_OFF + 192 * SK_STR) * 2)

template <int NTC>
__device__ __forceinline__ void flash_chunk(
    int jb, uint32_t skbase, uint32_t svbase,
    const uint32_t aQ[2][4], float O[4][4], float sums[4],
    const __half* __restrict__ bmA, const __half* __restrict__ bmB)
{
    constexpr int NS = (NTC + 1) / 2;
    uint32_t plo[NTC], phi[NTC];
    // S = QK^T -> +bias (f16x2) -> ex2 (f16x2) == PV A-fragments, all register-local
#pragma unroll
    for (int nt = 0; nt < NTC; nt++) {
        uint32_t k0, k1, k2, k3;
        ldsm4(k0, k1, k2, k3, skbase + (jb + nt * 8) * (SK_STR * 2));
        float acc[4] = {0.f, 0.f, 0.f, 0.f};
        mma16(acc, aQ[0][0], aQ[0][1], aQ[0][2], aQ[0][3], k0, k1);
        mma16(acc, aQ[1][0], aQ[1][1], aQ[1][2], aQ[1][3], k2, k3);
        int off = (jb + nt * 8) * 8;
        uint32_t s01 = hadd2(pack2(acc[0], acc[1]), *(const uint32_t*)&bmA[off]);
        uint32_t s23 = hadd2(pack2(acc[2], acc[3]), *(const uint32_t*)&bmB[off]);
        plo[nt] = hex2(s01);
        phi[nt] = hex2(s23);
    }
    // exact fp32 row sums via ones-MMA (sums over all lanes -> no shuffles ever)
#pragma unroll
    for (int s = 0; s < NS; s++) {
        uint32_t a2 = (2 * s + 1 < NTC) ? plo[2 * s + 1] : 0u;
        uint32_t a3 = (2 * s + 1 < NTC) ? phi[2 * s + 1] : 0u;
        mma16(sums, plo[2 * s], phi[2 * s], a2, a3, ONES2, ONES2);
    }
    // O += P V
#pragma unroll
    for (int nt = 0; nt < 4; nt++) {
        uint32_t v[8];
        uint32_t vb = svbase + (nt * 8) * (SV_STR * 2) + jb * 2;
        ldsm4(v[0], v[1], v[2], v[3], vb);
        if (NS > 2) ldsm4(v[4], v[5], v[6], v[7], vb + 64);
#pragma unroll
        for (int s = 0; s < NS; s++) {
            uint32_t a2 = (2 * s + 1 < NTC) ? plo[2 * s + 1] : 0u;
            uint32_t a3 = (2 * s + 1 < NTC) ? phi[2 * s + 1] : 0u;
            mma16(O[nt], plo[2 * s], phi[2 * s], a2, a3, v[2 * s], v[2 * s + 1]);
        }
    }
}

__global__ __launch_bounds__(384, 2)
void attn_flash() {
    extern __shared__ __half sh[];
    __half* sK  = sh;
    __half* sVt = sh + SVT_OFF;
    __half* sQ  = sh + SQ_OFF;

    const int tid = threadIdx.x;
    const int warp = tid >> 5, lane = tid & 31;
    const int g = lane >> 2, c4 = lane & 3;
    const int h = blockIdx.y;
    const int z = blockIdx.z;
    const int w = z >> 3, bat = z & 7;      // batches sharing a mask window adjacent (L2 reuse)
    const int b = bat * NW + w;
    const size_t kvbase = (size_t)(b * NHEAD + h) * (NTOK * HD);
    const int r0 = blockIdx.x * 192;

    // K fill (row 343 zeroed)
    for (int i = tid; i < 344 * 4; i += 384) {
        int n = i >> 2, q = (i & 3) * 8;
        uint4 val = (n < NTOK) ? *(const uint4*)&g_k[kvbase + (size_t)n * HD + q]
                               : make_uint4(0u, 0u, 0u, 0u);
        *(uint4*)&sK[n * SK_STR + q] = val;
    }
    // V transposed fill: sVt[d][n]
    for (int i = tid; i < NTOK * 16; i += 384) {
        int n = i / 16, dp = (i % 16) * 2;
        __half2 v = *(const __half2*)&g_v[kvbase + (size_t)n * HD + dp];
        sVt[dp * SV_STR + n] = __low2half(v);
        sVt[(dp + 1) * SV_STR + n] = __high2half(v);
    }
    for (int i = tid; i < 32 * 17; i += 384) {
        int d = i / 17, j = 343 + (i % 17);
        sVt[d * SV_STR + j] = __ushort_as_half(0);
    }
    // Q fill
    for (int i = tid; i < 192 * 4; i += 384) {
        int n = i >> 2, q = (i & 3) * 8;
        int r = r0 + n;
        uint4 val = (r < NTOK) ? *(const uint4*)&g_q[kvbase + (size_t)r * HD + q]
                               : make_uint4(0u, 0u, 0u, 0u);
        *(uint4*)&sQ[n * SK_STR + q] = val;
    }
    __syncthreads();

    const int qrow0 = r0 + warp * 16;
    if (qrow0 >= NTOK) return;   // dead warps: no CTA syncs remain

    // ldmatrix per-lane base addresses (bytes, shared space)
    const uint32_t skbase = smem_u32(sK)  + ((lane & 7) * SK_STR + (lane >> 3) * 8) * 2;
    const uint32_t svbase = smem_u32(sVt) + ((lane & 7) * SV_STR + (lane >> 3) * 8) * 2;

    // Q A-fragments via 2x ldmatrix.x4
    uint32_t aQ[2][4];
    {
        int row = warp * 16 + (lane & 7) + ((lane >> 3) & 1) * 8;
        int colp = ((lane >> 4) & 1) * 8;
        uint32_t qb = smem_u32(sQ) + (row * SK_STR + colp) * 2;
        ldsm4(aQ[0][0], aQ[0][1], aQ[0][2], aQ[0][3], qb);
        ldsm4(aQ[1][0], aQ[1][1], aQ[1][2], aQ[1][3], qb + 32);
    }

    // bias base pointers (fragment-order layout, fully coalesced loads)
    const int wh = w * NHEAD + h;
    const __half* bmA = g_bm + ((size_t)(wh * RBLK + (qrow0 >> 3)) * CPAIR) * 16 + c4 * 16 + g * 2;
    const __half* bmB = bmA + CPAIR * 16;

    float O[4][4] = {};
    float sums[4] = {};

#pragma unroll 1
    for (int jb = 0; jb < 320; jb += 64)
        flash_chunk<8>(jb, skbase, svbase, aQ, O, sums, bmA, bmB);
    flash_chunk<3>(320, skbase, svbase, aQ, O, sums, bmA, bmB);

    const float i0 = 1.f / sums[0], i1 = 1.f / sums[2];
    const int ra = qrow0 + g, rb = ra + 8;
#pragma unroll
    for (int nt = 0; nt < 4; nt++) {
        int dc = h * HD + nt * 8 + 2 * c4;
        if (ra < NTOK)
            *(uint32_t*)&g_att[((size_t)b * NTOK + ra) * DIM + dc] =
                pack2(O[nt][0] * i0, O[nt][1] * i0);
        if (rb < NTOK)
            *(uint32_t*)&g_att[((size_t)b * NTOK + rb) * DIM + dc] =
                pack2(O[nt][2] * i1, O[nt][3] * i1);
    }
}

// ---------------- launch ----------------
extern "C" void kernel_launch(void* const* d_in, const int* in_sizes, int n_in,
                              void* d_out, int out_size) {
    const float* x      = (const float*)d_in[0];
    const float* mask   = (const float*)d_in[1];
    const float* qkv_w  = (const float*)d_in[2];
    const float* qkv_b  = (const float*)d_in[3];
    const float* proj_w = (const float*)d_in[4];
    const float* proj_b = (const float*)d_in[5];
    const float* rpb    = (const float*)d_in[6];
    const int*   rel    = (const int*)d_in[7];
    float* out = (float*)d_out;

    const int qkv_smem  = (64 + 288) * GSTR * 2;
    const int proj_smem = (64 + 96) * GSTR * 2;
    cudaFuncSetAttribute(gemm_fp16<1>, cudaFuncAttributeMaxDynamicSharedMemorySize, qkv_smem);
    cudaFuncSetAttribute(gemm_fp16<0>, cudaFuncAttributeMaxDynamicSharedMemorySize, proj_smem);
    cudaFuncSetAttribute(attn_flash, cudaFuncAttributeMaxDynamicSharedMemorySize, FL_SMEM_BYTES);

    {
        const int total = NW * NHEAD * RBLK * CPAIR * 8;
        bm_kernel<<<(total + 255) / 256, 256>>>(mask, rpb, rel);
    }
    gemm_fp16<1><<<MROWS / 64, 256, qkv_smem>>>(x, qkv_w, qkv_b, nullptr);
    attn_flash<<<dim3(2, NHEAD, BWIN), 384, FL_SMEM_BYTES>>>();
    gemm_fp16<0><<<MROWS / 64, 256, proj_smem>>>(nullptr, proj_w, proj_b, out);
}

// round 12
// speedup vs baseline: 10.4631x; 1.1154x over previous
#include <cuda_runtime.h>
#include <cuda_fp16.h>
#include <cuda_bf16.h>
#include <cstdint>

// Problem constants
#define BWIN   512
#define NTOK   343
#define DIM    96
#define NHEAD  3
#define HD     32
#define NW     64
#define MROWS  (BWIN * NTOK)  // 175616
#define LOG2E  1.4426950408889634f
#define QSCALE (0.17677669529663687f * LOG2E)
#define RBLK   44     // row blocks of 8 (352 padded rows)
#define CPAIR  172    // column pairs (344 padded cols)

// ---------------- device scratch ----------------
__device__ __half g_q[BWIN * NHEAD * NTOK * HD];
__device__ __half g_k[BWIN * NHEAD * NTOK * HD];
__device__ __half g_v[BWIN * NHEAD * NTOK * HD];
__device__ __half g_att[BWIN * NTOK * DIM];
__device__ __half g_wqkv[288 * 96];
__device__ __half g_wproj[96 * 96];
// bias in fragment order: [w*3+h][rowblk][colpair][row%8][2], half
__device__ __half g_bm[NW * NHEAD * RBLK * CPAIR * 16];

// ---------------- helpers ----------------
__device__ __forceinline__ uint32_t pack2(float lo, float hi) {
    uint32_t r; asm("cvt.rn.f16x2.f32 %0, %1, %2;" : "=r"(r) : "f"(hi), "f"(lo)); return r;
}
__device__ __forceinline__ uint32_t hadd2(uint32_t a, uint32_t b) {
    uint32_t r; asm("add.rn.f16x2 %0, %1, %2;" : "=r"(r) : "r"(a), "r"(b)); return r;
}
__device__ __forceinline__ uint32_t hex2(uint32_t a) {
    uint32_t r; asm("ex2.approx.f16x2 %0, %1;" : "=r"(r) : "r"(a)); return r;
}
__device__ __forceinline__ void mma16(float* c, uint32_t a0, uint32_t a1, uint32_t a2, uint32_t a3,
                                      uint32_t b0, uint32_t b1) {
    asm volatile("mma.sync.aligned.m16n8k16.row.col.f32.f16.f16.f32 "
                 "{%0,%1,%2,%3}, {%4,%5,%6,%7}, {%8,%9}, {%0,%1,%2,%3};\n"
                 : "+f"(c[0]), "+f"(c[1]), "+f"(c[2]), "+f"(c[3])
                 : "r"(a0), "r"(a1), "r"(a2), "r"(a3), "r"(b0), "r"(b1));
}
__device__ __forceinline__ void ldsm4(uint32_t& r0, uint32_t& r1, uint32_t& r2, uint32_t& r3,
                                      uint32_t addr) {
    asm volatile("ldmatrix.sync.aligned.m8n8.x4.shared.b16 {%0,%1,%2,%3}, [%4];"
                 : "=r"(r0), "=r"(r1), "=r"(r2), "=r"(r3) : "r"(addr));
}
__device__ __forceinline__ void ldsm4t(uint32_t& r0, uint32_t& r1, uint32_t& r2, uint32_t& r3,
                                       uint32_t addr) {
    asm volatile("ldmatrix.sync.aligned.m8n8.x4.trans.shared.b16 {%0,%1,%2,%3}, [%4];"
                 : "=r"(r0), "=r"(r1), "=r"(r2), "=r"(r3) : "r"(addr));
}
__device__ __forceinline__ uint32_t smem_u32(const void* p) {
    return (uint32_t)__cvta_generic_to_shared(p);
}
#define ONES2 0x3C003C00u

// ---------------- kernel: convert weights to half (once per launch) ----------------
__global__ void prep_w(const float* __restrict__ qkv_w, const float* __restrict__ proj_w) {
    int i = blockIdx.x * blockDim.x + threadIdx.x;
    if (i < 288 * 96) g_wqkv[i] = __float2half(qkv_w[i]);
    if (i < 96 * 96)  g_wproj[i] = __float2half(proj_w[i]);
}

// ---------------- kernel: fused bias, fragment order, coalesced gathers ----------------
// one thread per (w,h,rowblk,colpair); loops the 8 rows; writes 32B contiguous.
__global__ void bm_kernel(const float* __restrict__ mask,
                          const float* __restrict__ rpb,
                          const int*   __restrict__ rel) {
    int idx = blockIdx.x * blockDim.x + threadIdx.x;
    const int total = NW * NHEAD * RBLK * CPAIR;
    if (idx >= total) return;
    int cp = idx % CPAIR;
    int t = idx / CPAIR;
    int rb = t % RBLK; t /= RBLK;
    int h = t % NHEAD; int w = t / NHEAD;
    const int c0 = cp * 2;
    uint32_t u[8];
#pragma unroll
    for (int i = 0; i < 8; i++) {
        int row = rb * 8 + i;
        float v0 = -60000.f, v1 = -60000.f;
        if (row < NTOK) {
            const float* mrow = &mask[(size_t)(w * NTOK + row) * NTOK];
            const int*   rrow = &rel[row * NTOK];
            v0 = (mrow[c0] + rpb[rrow[c0] * NHEAD + h]) * LOG2E;     // c0 <= 342
            if (c0 + 1 < NTOK)
                v1 = (mrow[c0 + 1] + rpb[rrow[c0 + 1] * NHEAD + h]) * LOG2E;
        }
        u[i] = pack2(v0, v1);
    }
    uint4* dst = (uint4*)&g_bm[(size_t)idx * 16];
    dst[0] = make_uint4(u[0], u[1], u[2], u[3]);
    dst[1] = make_uint4(u[4], u[5], u[6], u[7]);
}

// ---------------- fp16 GEMM with ldmatrix fragment loads ----------------
#define GSTR 104   // smem row stride in halves; 8-row ldsm groups cover all 32 banks
template <int EPI>
__global__ __launch_bounds__(256)
void gemm_fp16(const float* __restrict__ A,
               const float* __restrict__ bias,
               float* __restrict__ out) {
    constexpr int NCH = EPI ? 3 : 1;
    extern __shared__ __half sh[];
    __half* sA = sh;                 // [64][GSTR]
    __half* sW = sh + 64 * GSTR;     // [NCH*96][GSTR]
    const __half* Wsrc = EPI ? g_wqkv : g_wproj;

    const int tid = threadIdx.x;
    const int m0 = blockIdx.x * 64;

    if (EPI == 1) {
        for (int it = tid; it < 64 * 24; it += 256) {
            int row = it / 24, k4 = (it % 24) * 4;
            float4 a = *(const float4*)&A[(size_t)(m0 + row) * 96 + k4];
            *(uint32_t*)&sA[row * GSTR + k4]     = pack2(a.x, a.y);
            *(uint32_t*)&sA[row * GSTR + k4 + 2] = pack2(a.z, a.w);
        }
    } else {
        for (int it = tid; it < 64 * 12; it += 256) {
            int row = it / 12, k8 = (it % 12) * 8;
            *(uint4*)&sA[row * GSTR + k8] = *(const uint4*)&g_att[(size_t)(m0 + row) * 96 + k8];
        }
    }
    // W fill: plain half copies (12 uint4 per 96-half row)
    for (int it = tid; it < NCH * 96 * 12; it += 256) {
        int row = it / 12, k8 = (it % 12) * 8;
        *(uint4*)&sW[row * GSTR + k8] = *(const uint4*)&Wsrc[(size_t)row * 96 + k8];
    }
    __syncthreads();

    const int warp = tid >> 5, lane = tid & 31;
    const int g = lane >> 2, c4 = lane & 3;
    const int wm = warp & 3;   // 4 m-groups of 16 rows
    const int wn = warp >> 2;  // 2 n-groups of 48 cols per chunk

    // ldmatrix lane addresses
    const uint32_t aAddr = smem_u32(sA) +
        ((wm * 16 + (lane & 7) + ((lane >> 3) & 1) * 8) * GSTR + (lane >> 4) * 8) * 2;
    const uint32_t wBase = smem_u32(sW) +
        (((lane & 7) + (lane >> 4) * 8) * GSTR + ((lane >> 3) & 1) * 8) * 2;

    float acc[NCH][6][4];
#pragma unroll
    for (int ch = 0; ch < NCH; ch++)
#pragma unroll
        for (int nt = 0; nt < 6; nt++) {
            int cc = ch * 96 + wn * 48 + nt * 8 + 2 * c4;
            float b0 = bias[cc], b1 = bias[cc + 1];
            acc[ch][nt][0] = b0; acc[ch][nt][1] = b1;
            acc[ch][nt][2] = b0; acc[ch][nt][3] = b1;
        }

#pragma unroll
    for (int ks = 0; ks < 6; ks++) {
        uint32_t a0, a1, a2, a3;
        ldsm4(a0, a1, a2, a3, aAddr + ks * 32);
#pragma unroll
        for (int ch = 0; ch < NCH; ch++)
#pragma unroll
            for (int p = 0; p < 3; p++) {
                uint32_t b0, b1, b2, b3;
                ldsm4(b0, b1, b2, b3,
                      wBase + (ch * 96 + wn * 48 + p * 16) * (GSTR * 2) + ks * 32);
                mma16(acc[ch][2 * p],     a0, a1, a2, a3, b0, b1);
                mma16(acc[ch][2 * p + 1], a0, a1, a2, a3, b2, b3);
            }
    }

    int ra = m0 + wm * 16 + g;
    int rb = ra + 8;
    if (EPI == 0) {
#pragma unroll
        for (int nt = 0; nt < 6; nt++) {
            int cc = wn * 48 + nt * 8 + 2 * c4;
            *(float2*)&out[(size_t)ra * 96 + cc] = make_float2(acc[0][nt][0], acc[0][nt][1]);
            *(float2*)&out[(size_t)rb * 96 + cc] = make_float2(acc[0][nt][2], acc[0][nt][3]);
        }
    } else {
        int ba = ra / NTOK, ta = ra - ba * NTOK;
        int bb = rb / NTOK, tb = rb - bb * NTOK;
#pragma unroll
        for (int ch = 0; ch < NCH; ch++) {
            __half* dst = (ch == 0) ? g_q : (ch == 1) ? g_k : g_v;
            const float sc = (ch == 0) ? QSCALE : 1.0f;
#pragma unroll
            for (int nt = 0; nt < 6; nt++) {
                int cc = wn * 48 + nt * 8 + 2 * c4;
                int hh = cc >> 5, dd = cc & 31;
                *(uint32_t*)&dst[((size_t)(ba * NHEAD + hh) * NTOK + ta) * HD + dd] =
                    pack2(acc[ch][nt][0] * sc, acc[ch][nt][1] * sc);
                *(uint32_t*)&dst[((size_t)(bb * NHEAD + hh) * NTOK + tb) * HD + dd] =
                    pack2(acc[ch][nt][2] * sc, acc[ch][nt][3] * sc);
            }
        }
    }
}

// ---------------- flash attention: LDSM(+trans V) + f16x2 softmax + ones-MMA ----------------
#define SK_STR  40
#define SV_OFF  13760               // K: 344*40
#define SQ_OFF  (13760 + 14080)    // V: 352*40
#define FL_SMEM_BYTES ((SQ_OFF + 192 * SK_STR) * 2)   // 71,040 B

template <int NTC>
__device__ __forceinline__ void flash_chunk(
    int jb, uint32_t skbase, uint32_t svbase,
    const uint32_t aQ[2][4], float O[4][4], float sums[4],
    const __half* __restrict__ bmA, const __half* __restrict__ bmB)
{
    constexpr int NS = (NTC + 1) / 2;
    // prefetch bias fragments
    uint32_t bfA[NTC], bfB[NTC];
#pragma unroll
    for (int nt = 0; nt < NTC; nt++) {
        int off = (jb + nt * 8) * 8;
        bfA[nt] = *(const uint32_t*)&bmA[off];
        bfB[nt] = *(const uint32_t*)&bmB[off];
    }
    uint32_t plo[NTC], phi[NTC];
#pragma unroll
    for (int nt = 0; nt < NTC; nt++) {
        uint32_t k0, k1, k2, k3;
        ldsm4(k0, k1, k2, k3, skbase + (jb + nt * 8) * (SK_STR * 2));
        float acc[4] = {0.f, 0.f, 0.f, 0.f};
        mma16(acc, aQ[0][0], aQ[0][1], aQ[0][2], aQ[0][3], k0, k1);
        mma16(acc, aQ[1][0], aQ[1][1], aQ[1][2], aQ[1][3], k2, k3);
        plo[nt] = hex2(hadd2(pack2(acc[0], acc[1]), bfA[nt]));
        phi[nt] = hex2(hadd2(pack2(acc[2], acc[3]), bfB[nt]));
    }
    // exact fp32 row sums via ones-MMA
#pragma unroll
    for (int s = 0; s < NS; s++) {
        uint32_t a2 = (2 * s + 1 < NTC) ? plo[2 * s + 1] : 0u;
        uint32_t a3 = (2 * s + 1 < NTC) ? phi[2 * s + 1] : 0u;
        mma16(sums, plo[2 * s], phi[2 * s], a2, a3, ONES2, ONES2);
    }
    // O += P V  (V in natural [n][d] layout, loaded via ldmatrix.trans)
#pragma unroll
    for (int nt = 0; nt < 4; nt++) {
        uint32_t v[8];
        uint32_t vb = svbase + jb * (SK_STR * 2) + (nt * 8) * 2;
        ldsm4t(v[0], v[1], v[2], v[3], vb);
        if (NS > 2) ldsm4t(v[4], v[5], v[6], v[7], vb + 32 * (SK_STR * 2));
#pragma unroll
        for (int s = 0; s < NS; s++) {
            uint32_t a2 = (2 * s + 1 < NTC) ? plo[2 * s + 1] : 0u;
            uint32_t a3 = (2 * s + 1 < NTC) ? phi[2 * s + 1] : 0u;
            mma16(O[nt], plo[2 * s], phi[2 * s], a2, a3, v[2 * s], v[2 * s + 1]);
        }
    }
}

__global__ __launch_bounds__(384, 2)
void attn_flash() {
    extern __shared__ __half sh[];
    __half* sK = sh;
    __half* sV = sh + SV_OFF;
    __half* sQ = sh + SQ_OFF;

    const int tid = threadIdx.x;
    const int warp = tid >> 5, lane = tid & 31;
    const int g = lane >> 2, c4 = lane & 3;
    const int h = blockIdx.y;
    const int z = blockIdx.z;
    const int w = z >> 3, bat = z & 7;      // batches sharing a mask window adjacent (L2 reuse)
    const int b = bat * NW + w;
    const size_t kvbase = (size_t)(b * NHEAD + h) * (NTOK * HD);
    const int r0 = blockIdx.x * 192;

    // K fill (rows >= 343 zeroed)
    for (int i = tid; i < 344 * 4; i += 384) {
        int n = i >> 2, q = (i & 3) * 8;
        uint4 val = (n < NTOK) ? *(const uint4*)&g_k[kvbase + (size_t)n * HD + q]
                               : make_uint4(0u, 0u, 0u, 0u);
        *(uint4*)&sK[n * SK_STR + q] = val;
    }
    // V fill, natural layout, rows 343..351 zeroed
    for (int i = tid; i < 352 * 4; i += 384) {
        int n = i >> 2, q = (i & 3) * 8;
        uint4 val = (n < NTOK) ? *(const uint4*)&g_v[kvbase + (size_t)n * HD + q]
                               : make_uint4(0u, 0u, 0u, 0u);
        *(uint4*)&sV[n * SK_STR + q] = val;
    }
    // Q fill
    for (int i = tid; i < 192 * 4; i += 384) {
        int n = i >> 2, q = (i & 3) * 8;
        int r = r0 + n;
        uint4 val = (r < NTOK) ? *(const uint4*)&g_q[kvbase + (size_t)r * HD + q]
                               : make_uint4(0u, 0u, 0u, 0u);
        *(uint4*)&sQ[n * SK_STR + q] = val;
    }
    __syncthreads();

    const int qrow0 = r0 + warp * 16;
    if (qrow0 >= NTOK) return;   // dead warps: no CTA syncs remain

    // per-lane ldmatrix base addresses
    const uint32_t skbase = smem_u32(sK) + ((lane & 7) * SK_STR + (lane >> 3) * 8) * 2;
    const uint32_t svbase = smem_u32(sV) + (((lane & 7) + (lane >> 3) * 8) * SK_STR) * 2;

    // Q A-fragments via 2x ldmatrix.x4
    uint32_t aQ[2][4];
    {
        int row = warp * 16 + (lane & 7) + ((lane >> 3) & 1) * 8;
        int colp = ((lane >> 4) & 1) * 8;
        uint32_t qb = smem_u32(sQ) + (row * SK_STR + colp) * 2;
        ldsm4(aQ[0][0], aQ[0][1], aQ[0][2], aQ[0][3], qb);
        ldsm4(aQ[1][0], aQ[1][1], aQ[1][2], aQ[1][3], qb + 32);
    }

    // bias base pointers (fragment-order layout)
    const int wh = w * NHEAD + h;
    const __half* bmA = g_bm + ((size_t)(wh * RBLK + (qrow0 >> 3)) * CPAIR) * 16 + c4 * 16 + g * 2;
    const __half* bmB = bmA + CPAIR * 16;

    float O[4][4] = {};
    float sums[4] = {};

#pragma unroll 1
    for (int jb = 0; jb < 320; jb += 64)
        flash_chunk<8>(jb, skbase, svbase, aQ, O, sums, bmA, bmB);
    flash_chunk<3>(320, skbase, svbase, aQ, O, sums, bmA, bmB);

    const float i0 = 1.f / sums[0], i1 = 1.f / sums[2];
    const int ra = qrow0 + g, rb = ra + 8;
#pragma unroll
    for (int nt = 0; nt < 4; nt++) {
        int dc = h * HD + nt * 8 + 2 * c4;
        if (ra < NTOK)
            *(uint32_t*)&g_att[((size_t)b * NTOK + ra) * DIM + dc] =
                pack2(O[nt][0] * i0, O[nt][1] * i0);
        if (rb < NTOK)
            *(uint32_t*)&g_att[((size_t)b * NTOK + rb) * DIM + dc] =
                pack2(O[nt][2] * i1, O[nt][3] * i1);
    }
}

// ---------------- launch ----------------
extern "C" void kernel_launch(void* const* d_in, const int* in_sizes, int n_in,
                              void* d_out, int out_size) {
    const float* x      = (const float*)d_in[0];
    const float* mask   = (const float*)d_in[1];
    const float* qkv_w  = (const float*)d_in[2];
    const float* qkv_b  = (const float*)d_in[3];
    const float* proj_w = (const float*)d_in[4];
    const float* proj_b = (const float*)d_in[5];
    const float* rpb    = (const float*)d_in[6];
    const int*   rel    = (const int*)d_in[7];
    float* out = (float*)d_out;

    const int qkv_smem  = (64 + 288) * GSTR * 2;
    const int proj_smem = (64 + 96) * GSTR * 2;
    cudaFuncSetAttribute(gemm_fp16<1>, cudaFuncAttributeMaxDynamicSharedMemorySize, qkv_smem);
    cudaFuncSetAttribute(gemm_fp16<0>, cudaFuncAttributeMaxDynamicSharedMemorySize, proj_smem);
    cudaFuncSetAttribute(attn_flash, cudaFuncAttributeMaxDynamicSharedMemorySize, FL_SMEM_BYTES);

    prep_w<<<(288 * 96 + 255) / 256, 256>>>(qkv_w, proj_w);
    {
        const int total = NW * NHEAD * RBLK * CPAIR;
        bm_kernel<<<(total + 255) / 256, 256>>>(mask, rpb, rel);
    }
    gemm_fp16<1><<<MROWS / 64, 256, qkv_smem>>>(x, qkv_b, nullptr);
    attn_flash<<<dim3(2, NHEAD, BWIN), 384, FL_SMEM_BYTES>>>();
    gemm_fp16<0><<<MROWS / 64, 256, proj_smem>>>(nullptr, proj_b, out);
}

// round 14
// speedup vs baseline: 11.0798x; 1.0589x over previous
#include <cuda_runtime.h>
#include <cuda_fp16.h>
#include <cuda_bf16.h>
#include <cstdint>

// Problem constants
#define BWIN   512
#define NTOK   343
#define DIM    96
#define NHEAD  3
#define HD     32
#define NW     64
#define MROWS  (BWIN * NTOK)  // 175616
#define LOG2E  1.4426950408889634f
#define QSCALE (0.17677669529663687f * LOG2E)
#define RBLK   44     // row blocks of 8 (352 padded rows)
#define CPAIR  172    // column pairs (344 padded cols)

// ---------------- device scratch ----------------
__device__ __half g_q[BWIN * NHEAD * NTOK * HD];
__device__ __half g_k[BWIN * NHEAD * NTOK * HD];
__device__ __half g_v[BWIN * NHEAD * NTOK * HD];
__device__ __half g_att[BWIN * NTOK * DIM];
__device__ __half g_wqkv[288 * 96];
__device__ __half g_wproj[96 * 96];
// bias in fragment order: [w*3+h][rowblk][colpair][row%8][2], half
__device__ __half g_bm[NW * NHEAD * RBLK * CPAIR * 16];

// ---------------- helpers ----------------
__device__ __forceinline__ uint32_t pack2(float lo, float hi) {
    uint32_t r; asm("cvt.rn.f16x2.f32 %0, %1, %2;" : "=r"(r) : "f"(hi), "f"(lo)); return r;
}
__device__ __forceinline__ uint32_t hadd2(uint32_t a, uint32_t b) {
    uint32_t r; asm("add.rn.f16x2 %0, %1, %2;" : "=r"(r) : "r"(a), "r"(b)); return r;
}
__device__ __forceinline__ uint32_t hex2(uint32_t a) {
    uint32_t r; asm("ex2.approx.f16x2 %0, %1;" : "=r"(r) : "r"(a)); return r;
}
__device__ __forceinline__ void mma16(float* c, uint32_t a0, uint32_t a1, uint32_t a2, uint32_t a3,
                                      uint32_t b0, uint32_t b1) {
    asm volatile("mma.sync.aligned.m16n8k16.row.col.f32.f16.f16.f32 "
                 "{%0,%1,%2,%3}, {%4,%5,%6,%7}, {%8,%9}, {%0,%1,%2,%3};\n"
                 : "+f"(c[0]), "+f"(c[1]), "+f"(c[2]), "+f"(c[3])
                 : "r"(a0), "r"(a1), "r"(a2), "r"(a3), "r"(b0), "r"(b1));
}
__device__ __forceinline__ void ldsm4(uint32_t& r0, uint32_t& r1, uint32_t& r2, uint32_t& r3,
                                      uint32_t addr) {
    asm volatile("ldmatrix.sync.aligned.m8n8.x4.shared.b16 {%0,%1,%2,%3}, [%4];"
                 : "=r"(r0), "=r"(r1), "=r"(r2), "=r"(r3) : "r"(addr));
}
__device__ __forceinline__ void ldsm4t(uint32_t& r0, uint32_t& r1, uint32_t& r2, uint32_t& r3,
                                       uint32_t addr) {
    asm volatile("ldmatrix.sync.aligned.m8n8.x4.trans.shared.b16 {%0,%1,%2,%3}, [%4];"
                 : "=r"(r0), "=r"(r1), "=r"(r2), "=r"(r3) : "r"(addr));
}
__device__ __forceinline__ uint32_t smem_u32(const void* p) {
    return (uint32_t)__cvta_generic_to_shared(p);
}
#define ONES2 0x3C003C00u
#define BM_CTAS ((NW * NHEAD * RBLK * CPAIR + 255) / 256)   // 5676
#define PREP_CTAS ((288 * 96 + 255) / 256)                   // 108

// ---------------- fused: bias build + weight halving (independent work, one launch) ----
__global__ void prep_bm(const float* __restrict__ mask,
                        const float* __restrict__ rpb,
                        const int*   __restrict__ rel,
                        const float* __restrict__ qkv_w,
                        const float* __restrict__ proj_w) {
    if (blockIdx.x >= BM_CTAS) {
        int i = (blockIdx.x - BM_CTAS) * 256 + threadIdx.x;
        if (i < 288 * 96) g_wqkv[i] = __float2half(qkv_w[i]);
        if (i < 96 * 96)  g_wproj[i] = __float2half(proj_w[i]);
        return;
    }
    int idx = blockIdx.x * 256 + threadIdx.x;
    const int total = NW * NHEAD * RBLK * CPAIR;
    if (idx >= total) return;
    int cp = idx % CPAIR;
    int t = idx / CPAIR;
    int rb = t % RBLK; t /= RBLK;
    int h = t % NHEAD; int w = t / NHEAD;
    const int c0 = cp * 2;
    uint32_t u[8];
#pragma unroll
    for (int i = 0; i < 8; i++) {
        int row = rb * 8 + i;
        float v0 = -60000.f, v1 = -60000.f;
        if (row < NTOK) {
            const float* mrow = &mask[(size_t)(w * NTOK + row) * NTOK];
            const int*   rrow = &rel[row * NTOK];
            v0 = (mrow[c0] + rpb[rrow[c0] * NHEAD + h]) * LOG2E;
            if (c0 + 1 < NTOK)
                v1 = (mrow[c0 + 1] + rpb[rrow[c0 + 1] * NHEAD + h]) * LOG2E;
        }
        u[i] = pack2(v0, v1);
    }
    uint4* dst = (uint4*)&g_bm[(size_t)idx * 16];
    dst[0] = make_uint4(u[0], u[1], u[2], u[3]);
    dst[1] = make_uint4(u[4], u[5], u[6], u[7]);
}

// ---------------- qkv GEMM: 128 rows x 288 cols per CTA, 512 threads ----------------
#define GSTR 104
__global__ __launch_bounds__(512)
void gemm_qkv(const float* __restrict__ A, const float* __restrict__ bias) {
    extern __shared__ __half sh[];
    __half* sA = sh;                  // [128][GSTR]
    __half* sW = sh + 128 * GSTR;     // [288][GSTR]

    const int tid = threadIdx.x;
    const int m0 = blockIdx.x * 128;

    // A fill: fp32 -> half
    for (int it = tid; it < 128 * 24; it += 512) {
        int row = it / 24, k4 = (it % 24) * 4;
        float4 a = *(const float4*)&A[(size_t)(m0 + row) * 96 + k4];
        *(uint32_t*)&sA[row * GSTR + k4]     = pack2(a.x, a.y);
        *(uint32_t*)&sA[row * GSTR + k4 + 2] = pack2(a.z, a.w);
    }
    // W fill: half copies
    for (int it = tid; it < 288 * 12; it += 512) {
        int row = it / 12, k8 = (it % 12) * 8;
        *(uint4*)&sW[row * GSTR + k8] = *(const uint4*)&g_wqkv[(size_t)row * 96 + k8];
    }
    __syncthreads();

    const int warp = tid >> 5, lane = tid & 31;
    const int g = lane >> 2, c4 = lane & 3;
    const int wm = warp & 7;   // 8 m-groups of 16 rows
    const int wn = warp >> 3;  // 2 n-groups of 144 cols

    const uint32_t aAddr = smem_u32(sA) +
        ((wm * 16 + (lane & 7) + ((lane >> 3) & 1) * 8) * GSTR + (lane >> 4) * 8) * 2;
    const uint32_t wBase = smem_u32(sW) +
        (((lane & 7) + (lane >> 4) * 8) * GSTR + ((lane >> 3) & 1) * 8) * 2;

    float acc[18][4];
#pragma unroll
    for (int nt = 0; nt < 18; nt++) {
        int cc = wn * 144 + nt * 8 + 2 * c4;
        float b0 = bias[cc], b1 = bias[cc + 1];
        acc[nt][0] = b0; acc[nt][1] = b1;
        acc[nt][2] = b0; acc[nt][3] = b1;
    }

#pragma unroll
    for (int ks = 0; ks < 6; ks++) {
        uint32_t a0, a1, a2, a3;
        ldsm4(a0, a1, a2, a3, aAddr + ks * 32);
#pragma unroll
        for (int p = 0; p < 9; p++) {
            uint32_t b0, b1, b2, b3;
            ldsm4(b0, b1, b2, b3, wBase + (wn * 144 + p * 16) * (GSTR * 2) + ks * 32);
            mma16(acc[2 * p],     a0, a1, a2, a3, b0, b1);
            mma16(acc[2 * p + 1], a0, a1, a2, a3, b2, b3);
        }
    }

    int ra = m0 + wm * 16 + g;
    int rb = ra + 8;
    int ba = ra / NTOK, ta = ra - ba * NTOK;
    int bb = rb / NTOK, tb = rb - bb * NTOK;
#pragma unroll
    for (int nt = 0; nt < 18; nt++) {
        int cc = wn * 144 + nt * 8 + 2 * c4;
        int ch = cc / 96, ccl = cc - ch * 96;
        int hh = ccl >> 5, dd = ccl & 31;
        __half* dst = (ch == 0) ? g_q : (ch == 1) ? g_k : g_v;
        const float sc = (ch == 0) ? QSCALE : 1.0f;
        *(uint32_t*)&dst[((size_t)(ba * NHEAD + hh) * NTOK + ta) * HD + dd] =
            pack2(acc[nt][0] * sc, acc[nt][1] * sc);
        *(uint32_t*)&dst[((size_t)(bb * NHEAD + hh) * NTOK + tb) * HD + dd] =
            pack2(acc[nt][2] * sc, acc[nt][3] * sc);
    }
}

// ---------------- proj GEMM: 128 rows x 96 cols per CTA, 512 threads ----------------
__global__ __launch_bounds__(512)
void gemm_proj(const float* __restrict__ bias, float* __restrict__ out) {
    extern __shared__ __half sh[];
    __half* sA = sh;                  // [128][GSTR]
    __half* sW = sh + 128 * GSTR;     // [96][GSTR]

    const int tid = threadIdx.x;
    const int m0 = blockIdx.x * 128;

    for (int it = tid; it < 128 * 12; it += 512) {
        int row = it / 12, k8 = (it % 12) * 8;
        *(uint4*)&sA[row * GSTR + k8] = *(const uint4*)&g_att[(size_t)(m0 + row) * 96 + k8];
    }
    for (int it = tid; it < 96 * 12; it += 512) {
        int row = it / 12, k8 = (it % 12) * 8;
        *(uint4*)&sW[row * GSTR + k8] = *(const uint4*)&g_wproj[(size_t)row * 96 + k8];
    }
    __syncthreads();

    const int warp = tid >> 5, lane = tid & 31;
    const int g = lane >> 2, c4 = lane & 3;
    const int wm = warp & 7;   // 8 m-groups of 16 rows
    const int wn = warp >> 3;  // 2 n-groups of 48 cols

    const uint32_t aAddr = smem_u32(sA) +
        ((wm * 16 + (lane & 7) + ((lane >> 3) & 1) * 8) * GSTR + (lane >> 4) * 8) * 2;
    const uint32_t wBase = smem_u32(sW) +
        (((lane & 7) + (lane >> 4) * 8) * GSTR + ((lane >> 3) & 1) * 8) * 2;

    float acc[6][4];
#pragma unroll
    for (int nt = 0; nt < 6; nt++) {
        int cc = wn * 48 + nt * 8 + 2 * c4;
        float b0 = bias[cc], b1 = bias[cc + 1];
        acc[nt][0] = b0; acc[nt][1] = b1;
        acc[nt][2] = b0; acc[nt][3] = b1;
    }

#pragma unroll
    for (int ks = 0; ks < 6; ks++) {
        uint32_t a0, a1, a2, a3;
        ldsm4(a0, a1, a2, a3, aAddr + ks * 32);
#pragma unroll
        for (int p = 0; p < 3; p++) {
            uint32_t b0, b1, b2, b3;
            ldsm4(b0, b1, b2, b3, wBase + (wn * 48 + p * 16) * (GSTR * 2) + ks * 32);
            mma16(acc[2 * p],     a0, a1, a2, a3, b0, b1);
            mma16(acc[2 * p + 1], a0, a1, a2, a3, b2, b3);
        }
    }

    int ra = m0 + wm * 16 + g;
    int rb = ra + 8;
#pragma unroll
    for (int nt = 0; nt < 6; nt++) {
        int cc = wn * 48 + nt * 8 + 2 * c4;
        *(float2*)&out[(size_t)ra * 96 + cc] = make_float2(acc[nt][0], acc[nt][1]);
        *(float2*)&out[(size_t)rb * 96 + cc] = make_float2(acc[nt][2], acc[nt][3]);
    }
}

// ---------------- flash attention (unchanged from R11) ----------------
#define SK_STR  40
#define SV_OFF  13760               // K: 344*40
#define SQ_OFF  (13760 + 14080)    // V: 352*40
#define FL_SMEM_BYTES ((SQ_OFF + 192 * SK_STR) * 2)   // 71,040 B

template <int NTC>
__device__ __forceinline__ void flash_chunk(
    int jb, uint32_t skbase, uint32_t svbase,
    const uint32_t aQ[2][4], float O[4][4], float sums[4],
    const __half* __restrict__ bmA, const __half* __restrict__ bmB)
{
    constexpr int NS = (NTC + 1) / 2;
    uint32_t bfA[NTC], bfB[NTC];
#pragma unroll
    for (int nt = 0; nt < NTC; nt++) {
        int off = (jb + nt * 8) * 8;
        bfA[nt] = *(const uint32_t*)&bmA[off];
        bfB[nt] = *(const uint32_t*)&bmB[off];
    }
    uint32_t plo[NTC], phi[NTC];
#pragma unroll
    for (int nt = 0; nt < NTC; nt++) {
        uint32_t k0, k1, k2, k3;
        ldsm4(k0, k1, k2, k3, skbase + (jb + nt * 8) * (SK_STR * 2));
        float acc[4] = {0.f, 0.f, 0.f, 0.f};
        mma16(acc, aQ[0][0], aQ[0][1], aQ[0][2], aQ[0][3], k0, k1);
        mma16(acc, aQ[1][0], aQ[1][1], aQ[1][2], aQ[1][3], k2, k3);
        plo[nt] = hex2(hadd2(pack2(acc[0], acc[1]), bfA[nt]));
        phi[nt] = hex2(hadd2(pack2(acc[2], acc[3]), bfB[nt]));
    }
#pragma unroll
    for (int s = 0; s < NS; s++) {
        uint32_t a2 = (2 * s + 1 < NTC) ? plo[2 * s + 1] : 0u;
        uint32_t a3 = (2 * s + 1 < NTC) ? phi[2 * s + 1] : 0u;
        mma16(sums, plo[2 * s], phi[2 * s], a2, a3, ONES2, ONES2);
    }
#pragma unroll
    for (int nt = 0; nt < 4; nt++) {
        uint32_t v[8];
        uint32_t vb = svbase + jb * (SK_STR * 2) + (nt * 8) * 2;
        ldsm4t(v[0], v[1], v[2], v[3], vb);
        if (NS > 2) ldsm4t(v[4], v[5], v[6], v[7], vb + 32 * (SK_STR * 2));
#pragma unroll
        for (int s = 0; s < NS; s++) {
            uint32_t a2 = (2 * s + 1 < NTC) ? plo[2 * s + 1] : 0u;
            uint32_t a3 = (2 * s + 1 < NTC) ? phi[2 * s + 1] : 0u;
            mma16(O[nt], plo[2 * s], phi[2 * s], a2, a3, v[2 * s], v[2 * s + 1]);
        }
    }
}

__global__ __launch_bounds__(384, 2)
void attn_flash() {
    extern __shared__ __half sh[];
    __half* sK = sh;
    __half* sV = sh + SV_OFF;
    __half* sQ = sh + SQ_OFF;

    const int tid = threadIdx.x;
    const int warp = tid >> 5, lane = tid & 31;
    const int g = lane >> 2, c4 = lane & 3;
    const int h = blockIdx.y;
    const int z = blockIdx.z;
    const int w = z >> 3, bat = z & 7;      // batches sharing a mask window adjacent (L2 reuse)
    const int b = bat * NW + w;
    const size_t kvbase = (size_t)(b * NHEAD + h) * (NTOK * HD);
    const int r0 = blockIdx.x * 192;

    for (int i = tid; i < 344 * 4; i += 384) {
        int n = i >> 2, q = (i & 3) * 8;
        uint4 val = (n < NTOK) ? *(const uint4*)&g_k[kvbase + (size_t)n * HD + q]
                               : make_uint4(0u, 0u, 0u, 0u);
        *(uint4*)&sK[n * SK_STR + q] = val;
    }
    for (int i = tid; i < 352 * 4; i += 384) {
        int n = i >> 2, q = (i & 3) * 8;
        uint4 val = (n < NTOK) ? *(const uint4*)&g_v[kvbase + (size_t)n * HD + q]
                               : make_uint4(0u, 0u, 0u, 0u);
        *(uint4*)&sV[n * SK_STR + q] = val;
    }
    for (int i = tid; i < 192 * 4; i += 384) {
        int n = i >> 2, q = (i & 3) * 8;
        int r = r0 + n;
        uint4 val = (r < NTOK) ? *(const uint4*)&g_q[kvbase + (size_t)r * HD + q]
                               : make_uint4(0u, 0u, 0u, 0u);
        *(uint4*)&sQ[n * SK_STR + q] = val;
    }
    __syncthreads();

    const int qrow0 = r0 + warp * 16;
    if (qrow0 >= NTOK) return;

    const uint32_t skbase = smem_u32(sK) + ((lane & 7) * SK_STR + (lane >> 3) * 8) * 2;
    const uint32_t svbase = smem_u32(sV) + (((lane & 7) + (lane >> 3) * 8) * SK_STR) * 2;

    uint32_t aQ[2][4];
    {
        int row = warp * 16 + (lane & 7) + ((lane >> 3) & 1) * 8;
        int colp = ((lane >> 4) & 1) * 8;
        uint32_t qb = smem_u32(sQ) + (row * SK_STR + colp) * 2;
        ldsm4(aQ[0][0], aQ[0][1], aQ[0][2], aQ[0][3], qb);
        ldsm4(aQ[1][0], aQ[1][1], aQ[1][2], aQ[1][3], qb + 32);
    }

    const int wh = w * NHEAD + h;
    const __half* bmA = g_bm + ((size_t)(wh * RBLK + (qrow0 >> 3)) * CPAIR) * 16 + c4 * 16 + g * 2;
    const __half* bmB = bmA + CPAIR * 16;

    float O[4][4] = {};
    float sums[4] = {};

#pragma unroll 1
    for (int jb = 0; jb < 320; jb += 64)
        flash_chunk<8>(jb, skbase, svbase, aQ, O, sums, bmA, bmB);
    flash_chunk<3>(320, skbase, svbase, aQ, O, sums, bmA, bmB);

    const float i0 = 1.f / sums[0], i1 = 1.f / sums[2];
    const int ra = qrow0 + g, rb = ra + 8;
#pragma unroll
    for (int nt = 0; nt < 4; nt++) {
        int dc = h * HD + nt * 8 + 2 * c4;
        if (ra < NTOK)
            *(uint32_t*)&g_att[((size_t)b * NTOK + ra) * DIM + dc] =
                pack2(O[nt][0] * i0, O[nt][1] * i0);
        if (rb < NTOK)
            *(uint32_t*)&g_att[((size_t)b * NTOK + rb) * DIM + dc] =
                pack2(O[nt][2] * i1, O[nt][3] * i1);
    }
}

// ---------------- launch ----------------
extern "C" void kernel_launch(void* const* d_in, const int* in_sizes, int n_in,
                              void* d_out, int out_size) {
    const float* x      = (const float*)d_in[0];
    const float* mask   = (const float*)d_in[1];
    const float* qkv_w  = (const float*)d_in[2];
    const float* qkv_b  = (const float*)d_in[3];
    const float* proj_w = (const float*)d_in[4];
    const float* proj_b = (const float*)d_in[5];
    const float* rpb    = (const float*)d_in[6];
    const int*   rel    = (const int*)d_in[7];
    float* out = (float*)d_out;

    const int qkv_smem  = (128 + 288) * GSTR * 2;   // 86,528 B
    const int proj_smem = (128 + 96) * GSTR * 2;    // 46,592 B
    cudaFuncSetAttribute(gemm_qkv, cudaFuncAttributeMaxDynamicSharedMemorySize, qkv_smem);
    cudaFuncSetAttribute(gemm_proj, cudaFuncAttributeMaxDynamicSharedMemorySize, proj_smem);
    cudaFuncSetAttribute(attn_flash, cudaFuncAttributeMaxDynamicSharedMemorySize, FL_SMEM_BYTES);

    prep_bm<<<BM_CTAS + PREP_CTAS, 256>>>(mask, rpb, rel, qkv_w, proj_w);
    gemm_qkv<<<MROWS / 128, 512, qkv_smem>>>(x, qkv_b);
    attn_flash<<<dim3(2, NHEAD, BWIN), 384, FL_SMEM_BYTES>>>();
    gemm_proj<<<MROWS / 128, 512, proj_smem>>>(proj_b, out);
}